// round 9
// baseline (speedup 1.0000x reference)
#include <cuda_runtime.h>
#include <cuda_fp16.h>
#include <cstdint>

// Problem constants: B=2, S=1024, D=2048, F=8192, E=4, K=2
#define TT 2048
#define TD 2048
#define TF 8192
#define TE 4
#define NA 4096

#define KC 32           // K per stage

// GEMM1 smem layout (bytes):
//   A   ring3 @ 0      : stage = 128 rows * 80B        = 10240
//   B16 ring2 @ 30720  : stage = [G 32*144][U 32*144]  = 9216
//   B32 ring3 @ 49152  : stage = [G 32*272][U 32*272]  = 17408
//   rid @ 101376 (512B)
#define G1_A_ST   10240
#define G1_B16    30720
#define G1_B16_ST 9216
#define G1_B32    49152
#define G1_B32_ST 17408
#define G1_RID    101376
#define G1_SMEM   (101376 + 512)

// GEMM2 smem layout:
//   A   ring3 @ 0      : 10240/stage
//   B16 ring2 @ 30720  : [B0 32*144][B1 32*144] = 9216/stage
//   B32 ring3 @ 49152  : 32 * 528B = 16896/stage
#define G2_A_ST   10240
#define G2_B16    30720
#define G2_B16_ST 9216
#define G2_B32    49152
#define G2_B32_ST 16896
#define G2_SMEM   (49152 + 3*16896)

#define NX4 (TT*TD/4)

// ---------------- device scratch ----------------
__device__ int    g_counts[TE];
__device__ int    g_fill[TE];
__device__ int    g_offs[TE + 1];
__device__ int    g_eidx[NA];
__device__ float  g_gate[NA];
__device__ int    g_rowmap[NA];
__device__ float  g_rowgate[NA];
__device__ __half g_Xh[(size_t)TT * TD];
__device__ __half g_Hh[(size_t)NA * TF];
__device__ float  g_Y0[(size_t)NA * TD];
__device__ float  g_Y1[(size_t)NA * TD];

// ---------------- helpers ----------------
__device__ __forceinline__ uint32_t smem_u32(const void* p) {
    uint32_t a;
    asm("{ .reg .u64 t; cvta.to.shared.u64 t, %1; cvt.u32.u64 %0, t; }" : "=r"(a) : "l"(p));
    return a;
}
__device__ __forceinline__ void cpa16(uint32_t dst, const void* src, uint32_t valid) {
    asm volatile("cp.async.cg.shared.global [%0], [%1], 16, %2;" :: "r"(dst), "l"(src), "r"(valid) : "memory");
}
__device__ __forceinline__ void cpa_commit() { asm volatile("cp.async.commit_group;" ::: "memory"); }
__device__ __forceinline__ void cpa_wait1()  { asm volatile("cp.async.wait_group 1;" ::: "memory"); }
__device__ __forceinline__ void cpa_wait0()  { asm volatile("cp.async.wait_group 0;" ::: "memory"); }

__device__ __forceinline__ void ldmx4(uint32_t* r, uint32_t addr) {
    asm volatile("ldmatrix.sync.aligned.m8n8.x4.shared.b16 {%0,%1,%2,%3}, [%4];"
                 : "=r"(r[0]), "=r"(r[1]), "=r"(r[2]), "=r"(r[3]) : "r"(addr));
}
__device__ __forceinline__ void ldmx4t(uint32_t* r, uint32_t addr) {
    asm volatile("ldmatrix.sync.aligned.m8n8.x4.trans.shared.b16 {%0,%1,%2,%3}, [%4];"
                 : "=r"(r[0]), "=r"(r[1]), "=r"(r[2]), "=r"(r[3]) : "r"(addr));
}
__device__ __forceinline__ void mma_f16(float* c, const uint32_t* a, uint32_t b0, uint32_t b1) {
    asm volatile(
        "mma.sync.aligned.m16n8k16.row.col.f32.f16.f16.f32 "
        "{%0,%1,%2,%3}, {%4,%5,%6,%7}, {%8,%9}, {%0,%1,%2,%3};"
        : "+f"(c[0]), "+f"(c[1]), "+f"(c[2]), "+f"(c[3])
        : "r"(a[0]), "r"(a[1]), "r"(a[2]), "r"(a[3]), "r"(b0), "r"(b1));
}
__device__ __forceinline__ uint32_t packh2(float a, float b) {
    __half2 h = __floats2half2_rn(a, b);
    return *(uint32_t*)&h;
}
// convert 16 floats (4 x float4 at src,+16,+32,+48) -> 16 halfs (2 x uint4 at dst,+16)
__device__ __forceinline__ void cvt16(const char* src, char* dst) {
    float4 f0 = *(const float4*)(src);
    float4 f1 = *(const float4*)(src + 16);
    float4 f2 = *(const float4*)(src + 32);
    float4 f3 = *(const float4*)(src + 48);
    uint4 o0, o1;
    o0.x = packh2(f0.x, f0.y); o0.y = packh2(f0.z, f0.w);
    o0.z = packh2(f1.x, f1.y); o0.w = packh2(f1.z, f1.w);
    o1.x = packh2(f2.x, f2.y); o1.y = packh2(f2.z, f2.w);
    o1.z = packh2(f3.x, f3.y); o1.w = packh2(f3.z, f3.w);
    *(uint4*)(dst) = o0;
    *(uint4*)(dst + 16) = o1;
}

// ---------------- routing ----------------
__global__ void zero_kernel() {
    int i = threadIdx.x;
    if (i < TE) { g_counts[i] = 0; g_fill[i] = 0; }
}

__global__ void router_kernel(const float* __restrict__ x, const float* __restrict__ Wr) {
    int gw   = (int)((blockIdx.x * blockDim.x + threadIdx.x) >> 5);
    int lane = threadIdx.x & 31;
    if (gw >= TT) return;
    const float* xr = x + (size_t)gw * TD;
    float a0 = 0.f, a1 = 0.f, a2 = 0.f, a3 = 0.f;
    for (int d = lane; d < TD; d += 32) {
        float xv = xr[d];
        float4 w = *(const float4*)(Wr + d * 4);
        a0 += xv * w.x; a1 += xv * w.y; a2 += xv * w.z; a3 += xv * w.w;
    }
    #pragma unroll
    for (int o = 16; o; o >>= 1) {
        a0 += __shfl_xor_sync(0xffffffffu, a0, o);
        a1 += __shfl_xor_sync(0xffffffffu, a1, o);
        a2 += __shfl_xor_sync(0xffffffffu, a2, o);
        a3 += __shfl_xor_sync(0xffffffffu, a3, o);
    }
    if (lane == 0) {
        float l[4] = {a0, a1, a2, a3};
        float m = fmaxf(fmaxf(l[0], l[1]), fmaxf(l[2], l[3]));
        float p[4]; float s = 0.f;
        #pragma unroll
        for (int i = 0; i < 4; i++) { p[i] = __expf(l[i] - m); s += p[i]; }
        float inv = 1.0f / s;
        int i0 = 0;
        #pragma unroll
        for (int i = 1; i < 4; i++) if (p[i] > p[i0]) i0 = i;
        int i1 = (i0 == 0) ? 1 : 0;
        #pragma unroll
        for (int i = 0; i < 4; i++) if (i != i0 && p[i] > p[i1]) i1 = i;
        g_eidx[gw * 2]     = i0; g_gate[gw * 2]     = p[i0] * inv;
        g_eidx[gw * 2 + 1] = i1; g_gate[gw * 2 + 1] = p[i1] * inv;
        atomicAdd(&g_counts[i0], 1);
        atomicAdd(&g_counts[i1], 1);
    }
}

__global__ void offsets_kernel() {
    if (threadIdx.x == 0) {
        int s = 0;
        for (int e = 0; e < TE; e++) { g_offs[e] = s; s += g_counts[e]; }
        g_offs[TE] = s;
    }
}

__global__ void scatter_kernel() {
    int a = blockIdx.x * blockDim.x + threadIdx.x;
    if (a >= NA) return;
    int e = g_eidx[a];
    int pos = g_offs[e] + atomicAdd(&g_fill[e], 1);
    g_rowmap[pos]  = a;
    g_rowgate[pos] = g_gate[a];
}

// ---------------- prep: x fp32 -> fp16 only ----------------
__global__ void cvt_x_kernel(const float4* __restrict__ x) {
    int i = blockIdx.x * blockDim.x + threadIdx.x;
    if (i >= NX4) return;
    float4 v = x[i];
    uint2 o;
    o.x = packh2(v.x, v.y);
    o.y = packh2(v.z, v.w);
    ((uint2*)g_Xh)[i] = o;
}

// ---------------- GEMM1: H = silu(Xe*Wg) * (Xe*Wu) ----------------
// fp32 weights streamed; in-pipeline fp32->fp16 conversion.
// CTA tile M=128 x N=64 (G and U). 8 warps (4m x 2n), warp tile 32x32 each.
__global__ __launch_bounds__(256, 2) void gemm1_kernel(
    const float* __restrict__ Wg, const float* __restrict__ Wu) {
    const int e    = blockIdx.z;
    const int cnt  = g_counts[e];
    const int row0 = blockIdx.x * 128;
    if (row0 >= cnt) return;
    const int seg = g_offs[e];
    const int f0  = blockIdx.y * 64;

    extern __shared__ char sm[];
    int* rid = (int*)(sm + G1_RID);

    const int tid = threadIdx.x, lane = tid & 31, warp = tid >> 5;
    const int grp = lane >> 2, t4 = lane & 3;

    if (tid < 128) {
        int r = row0 + tid;
        rid[tid] = (r < cnt) ? (g_rowmap[seg + r] >> 1) : -1;
    }
    __syncthreads();

    const uint32_t smb = smem_u32(sm);

    // A loader map: row = tid>>1, 16 halfs at (tid&1)*16
    const int arow = tid >> 1;
    const int ahh  = (tid & 1) * 16;
    const int tok  = rid[arow];
    const uint32_t aval = (tok >= 0) ? 16u : 0u;
    const __half* ap = g_Xh + (size_t)(tok < 0 ? 0 : tok) * TD + ahh;
    const uint32_t aoffB = (uint32_t)(arow * 80 + (tid & 1) * 32);

    // B loader/converter map: m = tid>>7 (0=G,1=U), row = (tid&127)>>2, c4 = tid&3
    const int bm   = tid >> 7;
    const int brow = (tid & 127) >> 2;
    const int bc4  = tid & 3;
    const float* bp = (bm ? Wu : Wg) + ((size_t)e * TD + brow) * TF + f0 + bc4 * 16;
    const uint32_t b32off = (uint32_t)(bm * 8704 + brow * 272 + bc4 * 64);
    const uint32_t b16off = (uint32_t)(bm * 4608 + brow * 144 + bc4 * 32);

    // prologue: A stages 0,1 -> slots 0,1 ; B32 stages 0,1,2 -> slots 0,1,2
    #pragma unroll
    for (int s = 0; s < 2; s++) {
        uint32_t ad = smb + s * G1_A_ST + aoffB;
        cpa16(ad,      ap + s * KC,     aval);
        cpa16(ad + 16, ap + s * KC + 8, aval);
    }
    #pragma unroll
    for (int s = 0; s < 3; s++) {
        uint32_t bd = smb + G1_B32 + s * G1_B32_ST + b32off;
        const float* bsrc = bp + (size_t)(s * KC) * TF;
        #pragma unroll
        for (int q = 0; q < 4; q++) cpa16(bd + q * 16, bsrc + q * 4, 16u);
    }
    cpa_commit();
    cpa_wait0();
    __syncthreads();
    // pre-loop: convert stage 0 -> B16 slot 0 (published by loop's first barrier)
    cvt16(sm + G1_B32 + b32off, sm + G1_B16 + b16off);

    float accG[2][4][4], accU[2][4][4];
    #pragma unroll
    for (int i = 0; i < 2; i++)
        #pragma unroll
        for (int j = 0; j < 4; j++)
            #pragma unroll
            for (int q = 0; q < 4; q++) { accG[i][j][q] = 0.f; accU[i][j][q] = 0.f; }

    const int mrow0 = (warp & 3) * 32;
    const int ncol0 = (warp >> 2) * 32;
    const int aR = mrow0 + ((lane >> 3) & 1) * 8 + (lane & 7);
    const int aC = (lane >> 4) * 8;
    const int bR = ((lane >> 3) & 1) * 8 + (lane & 7);
    const int bC = ncol0 + (lane >> 4) * 8;

    const int NC = TD / KC;   // 64
    #pragma unroll 1
    for (int i = 0; i < NC; i++) {
        cpa_wait1();
        __syncthreads();
        const uint32_t aS  = smb + (i % 3) * G1_A_ST;
        const uint32_t b16 = smb + G1_B16 + (i & 1) * G1_B16_ST;

        // ks = 0
        {
            uint32_t a[2][4];
            #pragma unroll
            for (int mi = 0; mi < 2; mi++)
                ldmx4(a[mi], aS + (aR + mi * 16) * 80 + aC * 2);
            uint32_t bg[2][4], bu[2][4];
            #pragma unroll
            for (int p = 0; p < 2; p++) {
                uint32_t ro = bR * 144 + (bC + p * 16) * 2;
                ldmx4t(bg[p], b16 + ro);
                ldmx4t(bu[p], b16 + 4608 + ro);
            }
            #pragma unroll
            for (int p = 0; p < 2; p++)
                #pragma unroll
                for (int sub = 0; sub < 2; sub++) {
                    const int ni = p * 2 + sub;
                    #pragma unroll
                    for (int mi = 0; mi < 2; mi++) {
                        mma_f16(accG[mi][ni], a[mi], bg[p][sub * 2], bg[p][sub * 2 + 1]);
                        mma_f16(accU[mi][ni], a[mi], bu[p][sub * 2], bu[p][sub * 2 + 1]);
                    }
                }
        }

        // convert stage i+1 (hidden under tensor work)
        if (i + 1 < NC)
            cvt16(sm + G1_B32 + ((i + 1) % 3) * G1_B32_ST + b32off,
                  sm + G1_B16 + ((i + 1) & 1) * G1_B16_ST + b16off);
        // issue next loads: A stage i+2, B32 stage i+3
        if (i + 2 < NC) {
            uint32_t ad = smb + ((i + 2) % 3) * G1_A_ST + aoffB;
            cpa16(ad,      ap + (i + 2) * KC,     aval);
            cpa16(ad + 16, ap + (i + 2) * KC + 8, aval);
        }
        if (i + 3 < NC) {
            uint32_t bd = smb + G1_B32 + ((i + 3) % 3) * G1_B32_ST + b32off;
            const float* bsrc = bp + (size_t)((i + 3) * KC) * TF;
            #pragma unroll
            for (int q = 0; q < 4; q++) cpa16(bd + q * 16, bsrc + q * 4, 16u);
        }
        cpa_commit();

        // ks = 1
        {
            uint32_t a[2][4];
            #pragma unroll
            for (int mi = 0; mi < 2; mi++)
                ldmx4(a[mi], aS + (aR + mi * 16) * 80 + (aC + 16) * 2);
            uint32_t bg[2][4], bu[2][4];
            #pragma unroll
            for (int p = 0; p < 2; p++) {
                uint32_t ro = (bR + 16) * 144 + (bC + p * 16) * 2;
                ldmx4t(bg[p], b16 + ro);
                ldmx4t(bu[p], b16 + 4608 + ro);
            }
            #pragma unroll
            for (int p = 0; p < 2; p++)
                #pragma unroll
                for (int sub = 0; sub < 2; sub++) {
                    const int ni = p * 2 + sub;
                    #pragma unroll
                    for (int mi = 0; mi < 2; mi++) {
                        mma_f16(accG[mi][ni], a[mi], bg[p][sub * 2], bg[p][sub * 2 + 1]);
                        mma_f16(accU[mi][ni], a[mi], bu[p][sub * 2], bu[p][sub * 2 + 1]);
                    }
                }
        }
    }

    // epilogue: h = silu(g)*u -> g_Hh (fp16)
    #pragma unroll
    for (int mi = 0; mi < 2; mi++) {
        const int rl = (warp & 3) * 32 + mi * 16 + grp;
        const int r0 = row0 + rl, r1 = row0 + rl + 8;
        #pragma unroll
        for (int ni = 0; ni < 4; ni++) {
            const int col = f0 + (warp >> 2) * 32 + ni * 8 + t4 * 2;
            if (r0 < cnt) {
                float gg0 = accG[mi][ni][0], uu0 = accU[mi][ni][0];
                float gg1 = accG[mi][ni][1], uu1 = accU[mi][ni][1];
                float h0 = __fdividef(gg0 * uu0, 1.0f + __expf(-gg0));
                float h1 = __fdividef(gg1 * uu1, 1.0f + __expf(-gg1));
                *(__half2*)&g_Hh[(size_t)(seg + r0) * TF + col] = __floats2half2_rn(h0, h1);
            }
            if (r1 < cnt) {
                float gg0 = accG[mi][ni][2], uu0 = accU[mi][ni][2];
                float gg1 = accG[mi][ni][3], uu1 = accU[mi][ni][3];
                float h0 = __fdividef(gg0 * uu0, 1.0f + __expf(-gg0));
                float h1 = __fdividef(gg1 * uu1, 1.0f + __expf(-gg1));
                *(__half2*)&g_Hh[(size_t)(seg + r1) * TF + col] = __floats2half2_rn(h0, h1);
            }
        }
    }
}

// ---------------- GEMM2: Y = gate * (H * Wd)  [split-K x2, fp32 weights] ----------------
// CTA tile M=128 x N=128. 8 warps (4m x 2n), warp tile 32x64. y = npanel*2 + kslice.
__global__ __launch_bounds__(256, 2) void gemm2_kernel(const float* __restrict__ Wd) {
    const int e    = blockIdx.z;
    const int cnt  = g_counts[e];
    const int row0 = blockIdx.x * 128;
    if (row0 >= cnt) return;
    const int seg = g_offs[e];
    const int n0  = (blockIdx.y >> 1) * 128;
    const int ksl = blockIdx.y & 1;
    const int k0  = ksl * (TF / 2);
    float* Yout = ksl ? g_Y1 : g_Y0;

    extern __shared__ char sm[];
    const int tid = threadIdx.x, lane = tid & 31, warp = tid >> 5;
    const int grp = lane >> 2, t4 = lane & 3;
    const uint32_t smb = smem_u32(sm);

    // A loader map
    const int arow = tid >> 1;
    const int ahh  = (tid & 1) * 16;
    const uint32_t aval = (row0 + arow < cnt) ? 16u : 0u;
    const __half* ap = g_Hh + (size_t)(seg + ((row0 + arow < cnt) ? row0 + arow : 0)) * TF + k0 + ahh;
    const uint32_t aoffB = (uint32_t)(arow * 80 + (tid & 1) * 32);

    // B loader/converter map: row = tid>>3 (0..31), c8 = tid&7 (16 floats each)
    const int brow = tid >> 3;
    const int bc8  = tid & 7;
    const float* bp = Wd + ((size_t)e * TF + k0 + brow) * TD + n0 + bc8 * 16;
    const uint32_t b32off = (uint32_t)(brow * 528 + bc8 * 64);
    const uint32_t b16off = (bc8 < 4)
        ? (uint32_t)(brow * 144 + bc8 * 32)
        : (uint32_t)(4608 + brow * 144 + (bc8 - 4) * 32);

    #pragma unroll
    for (int s = 0; s < 2; s++) {
        uint32_t ad = smb + s * G2_A_ST + aoffB;
        cpa16(ad,      ap + s * KC,     aval);
        cpa16(ad + 16, ap + s * KC + 8, aval);
    }
    #pragma unroll
    for (int s = 0; s < 3; s++) {
        uint32_t bd = smb + G2_B32 + s * G2_B32_ST + b32off;
        const float* bsrc = bp + (size_t)(s * KC) * TD;
        #pragma unroll
        for (int q = 0; q < 4; q++) cpa16(bd + q * 16, bsrc + q * 4, 16u);
    }
    cpa_commit();
    cpa_wait0();
    __syncthreads();
    cvt16(sm + G2_B32 + b32off, sm + G2_B16 + b16off);

    float acc[2][8][4];
    #pragma unroll
    for (int i = 0; i < 2; i++)
        #pragma unroll
        for (int j = 0; j < 8; j++)
            #pragma unroll
            for (int q = 0; q < 4; q++) acc[i][j][q] = 0.f;

    const int mrow0 = (warp & 3) * 32;
    const uint32_t sBsel = (warp >> 2) ? 4608u : 0u;
    const int aR = mrow0 + ((lane >> 3) & 1) * 8 + (lane & 7);
    const int aC = (lane >> 4) * 8;
    const int bR = ((lane >> 3) & 1) * 8 + (lane & 7);
    const int bC = (lane >> 4) * 8;

    const int NC = (TF / 2) / KC;   // 128
    #pragma unroll 1
    for (int i = 0; i < NC; i++) {
        cpa_wait1();
        __syncthreads();
        const uint32_t aS  = smb + (i % 3) * G2_A_ST;
        const uint32_t b16 = smb + G2_B16 + (i & 1) * G2_B16_ST + sBsel;

        // ks = 0
        {
            uint32_t a[2][4];
            #pragma unroll
            for (int mi = 0; mi < 2; mi++)
                ldmx4(a[mi], aS + (aR + mi * 16) * 80 + aC * 2);
            #pragma unroll
            for (int p = 0; p < 4; p++) {
                uint32_t bb[4];
                ldmx4t(bb, b16 + bR * 144 + (bC + p * 16) * 2);
                #pragma unroll
                for (int sub = 0; sub < 2; sub++) {
                    const int ni = p * 2 + sub;
                    #pragma unroll
                    for (int mi = 0; mi < 2; mi++)
                        mma_f16(acc[mi][ni], a[mi], bb[sub * 2], bb[sub * 2 + 1]);
                }
            }
        }

        if (i + 1 < NC)
            cvt16(sm + G2_B32 + ((i + 1) % 3) * G2_B32_ST + b32off,
                  sm + G2_B16 + ((i + 1) & 1) * G2_B16_ST + b16off);
        if (i + 2 < NC) {
            uint32_t ad = smb + ((i + 2) % 3) * G2_A_ST + aoffB;
            cpa16(ad,      ap + (i + 2) * KC,     aval);
            cpa16(ad + 16, ap + (i + 2) * KC + 8, aval);
        }
        if (i + 3 < NC) {
            uint32_t bd = smb + G2_B32 + ((i + 3) % 3) * G2_B32_ST + b32off;
            const float* bsrc = bp + (size_t)((i + 3) * KC) * TD;
            #pragma unroll
            for (int q = 0; q < 4; q++) cpa16(bd + q * 16, bsrc + q * 4, 16u);
        }
        cpa_commit();

        // ks = 1
        {
            uint32_t a[2][4];
            #pragma unroll
            for (int mi = 0; mi < 2; mi++)
                ldmx4(a[mi], aS + (aR + mi * 16) * 80 + (aC + 16) * 2);
            #pragma unroll
            for (int p = 0; p < 4; p++) {
                uint32_t bb[4];
                ldmx4t(bb, b16 + (bR + 16) * 144 + (bC + p * 16) * 2);
                #pragma unroll
                for (int sub = 0; sub < 2; sub++) {
                    const int ni = p * 2 + sub;
                    #pragma unroll
                    for (int mi = 0; mi < 2; mi++)
                        mma_f16(acc[mi][ni], a[mi], bb[sub * 2], bb[sub * 2 + 1]);
                }
            }
        }
    }

    // epilogue: scale by gate, scatter
    #pragma unroll
    for (int mi = 0; mi < 2; mi++) {
        const int rl = (warp & 3) * 32 + mi * 16 + grp;
        const int r0 = row0 + rl, r1 = row0 + rl + 8;
        int a0i = 0, a1i = 0; float w0 = 0.f, w1 = 0.f;
        if (r0 < cnt) { a0i = g_rowmap[seg + r0]; w0 = g_rowgate[seg + r0]; }
        if (r1 < cnt) { a1i = g_rowmap[seg + r1]; w1 = g_rowgate[seg + r1]; }
        #pragma unroll
        for (int ni = 0; ni < 8; ni++) {
            const int col = n0 + (warp >> 2) * 64 + ni * 8 + t4 * 2;
            if (r0 < cnt) {
                float2 v; v.x = w0 * acc[mi][ni][0]; v.y = w0 * acc[mi][ni][1];
                *(float2*)&Yout[(size_t)a0i * TD + col] = v;
            }
            if (r1 < cnt) {
                float2 v; v.x = w1 * acc[mi][ni][2]; v.y = w1 * acc[mi][ni][3];
                *(float2*)&Yout[(size_t)a1i * TD + col] = v;
            }
        }
    }
}

// ---------------- combine ----------------
__global__ void combine_kernel(float* __restrict__ out) {
    int i = blockIdx.x * blockDim.x + threadIdx.x;
    if (i >= TT * TD) return;
    int t = i >> 11;
    int d = i & (TD - 1);
    size_t i0 = (size_t)(2 * t) * TD + d;
    size_t i1 = (size_t)(2 * t + 1) * TD + d;
    out[i] = (g_Y0[i0] + g_Y1[i0]) + (g_Y0[i1] + g_Y1[i1]);
}

// ---------------- launch ----------------
extern "C" void kernel_launch(void* const* d_in, const int* in_sizes, int n_in,
                              void* d_out, int out_size) {
    const float* x  = (const float*)d_in[0];
    const float* Wr = (const float*)d_in[1];
    const float* Wg = (const float*)d_in[2];
    const float* Wu = (const float*)d_in[3];
    const float* Wd = (const float*)d_in[4];
    float* out = (float*)d_out;

    static int attr_done = 0;
    if (!attr_done) {
        cudaFuncSetAttribute(gemm1_kernel, cudaFuncAttributeMaxDynamicSharedMemorySize, G1_SMEM);
        cudaFuncSetAttribute(gemm2_kernel, cudaFuncAttributeMaxDynamicSharedMemorySize, G2_SMEM);
        attr_done = 1;
    }

    zero_kernel<<<1, 32>>>();
    router_kernel<<<TT / 8, 256>>>(x, Wr);
    offsets_kernel<<<1, 1>>>();
    scatter_kernel<<<NA / 256, 256>>>();
    cvt_x_kernel<<<(NX4 + 255) / 256, 256>>>((const float4*)x);

    gemm1_kernel<<<dim3(16, TF / 64, TE), 256, G1_SMEM>>>(Wg, Wu);
    gemm2_kernel<<<dim3(16, (TD / 128) * 2, TE), 256, G2_SMEM>>>(Wd);

    combine_kernel<<<(TT * TD) / 256, 256>>>(out);
}

// round 11
// speedup vs baseline: 1.4620x; 1.4620x over previous
#include <cuda_runtime.h>
#include <cuda_fp16.h>
#include <cstdint>

// Problem constants: B=2, S=1024, D=2048, F=8192, E=4, K=2
#define TT 2048
#define TD 2048
#define TF 8192
#define TE 4
#define NA 4096

#define KC 32           // K per stage (fp16)
#define NSTG 4

// GEMM1 smem (halfs/stage): A[128][40] + G[32][72] + U[32][72]
#define G1_STGH (128*40 + 32*72 + 32*72)    // 9728 halfs = 19456 B
#define G1_GB (128*40)                      // 5120
#define G1_UB (128*40 + 32*72)              // 7424
#define G1_SMEM (G1_STGH*NSTG*2 + 512)

// GEMM2 smem (halfs/stage): A[128][40] + B0[32][72] + B1[32][72]
#define G2_STGH G1_STGH
#define G2_B0 (128*40)
#define G2_B1 (128*40 + 32*72)
#define G2_SMEM (G2_STGH*NSTG*2)

#define NX4 (TT*TD/4)
#define NW4 (TE*TD*TF/4)

// gemm1 grid.y: 128 GEMM panels + 4 cvt panels (x16 x4 = 256 cvt CTAs)
#define G1_NYC 4

// ---------------- device scratch ----------------
__device__ int    g_counts[TE];
__device__ int    g_fill[TE];
__device__ int    g_offs[TE + 1];
__device__ int    g_eidx[NA];
__device__ float  g_gate[NA];
__device__ int    g_rowmap[NA];
__device__ float  g_rowgate[NA];
__device__ __half g_Xh[(size_t)TT * TD];
__device__ __half g_Wgh[(size_t)TE * TD * TF];
__device__ __half g_Wuh[(size_t)TE * TD * TF];
__device__ __half g_Wdh[(size_t)TE * TF * TD];
__device__ __half g_Hh[(size_t)NA * TF];
__device__ float  g_Y0[(size_t)NA * TD];    // split-K slice 0
__device__ float  g_Y1[(size_t)NA * TD];    // split-K slice 1

// ---------------- helpers ----------------
__device__ __forceinline__ uint32_t smem_u32(const void* p) {
    uint32_t a;
    asm("{ .reg .u64 t; cvta.to.shared.u64 t, %1; cvt.u32.u64 %0, t; }" : "=r"(a) : "l"(p));
    return a;
}
__device__ __forceinline__ void cpa16(uint32_t dst, const void* src, uint32_t valid) {
    asm volatile("cp.async.cg.shared.global [%0], [%1], 16, %2;" :: "r"(dst), "l"(src), "r"(valid) : "memory");
}
__device__ __forceinline__ void cpa_commit() { asm volatile("cp.async.commit_group;" ::: "memory"); }
__device__ __forceinline__ void cpa_wait2()  { asm volatile("cp.async.wait_group 2;" ::: "memory"); }

__device__ __forceinline__ void ldmx4(uint32_t* r, uint32_t addr) {
    asm volatile("ldmatrix.sync.aligned.m8n8.x4.shared.b16 {%0,%1,%2,%3}, [%4];"
                 : "=r"(r[0]), "=r"(r[1]), "=r"(r[2]), "=r"(r[3]) : "r"(addr));
}
__device__ __forceinline__ void ldmx4t(uint32_t* r, uint32_t addr) {
    asm volatile("ldmatrix.sync.aligned.m8n8.x4.trans.shared.b16 {%0,%1,%2,%3}, [%4];"
                 : "=r"(r[0]), "=r"(r[1]), "=r"(r[2]), "=r"(r[3]) : "r"(addr));
}
__device__ __forceinline__ void mma_f16(float* c, const uint32_t* a, uint32_t b0, uint32_t b1) {
    asm volatile(
        "mma.sync.aligned.m16n8k16.row.col.f32.f16.f16.f32 "
        "{%0,%1,%2,%3}, {%4,%5,%6,%7}, {%8,%9}, {%0,%1,%2,%3};"
        : "+f"(c[0]), "+f"(c[1]), "+f"(c[2]), "+f"(c[3])
        : "r"(a[0]), "r"(a[1]), "r"(a[2]), "r"(a[3]), "r"(b0), "r"(b1));
}
__device__ __forceinline__ uint32_t packh2(float a, float b) {
    __half2 h = __floats2half2_rn(a, b);
    return *(uint32_t*)&h;
}

// ---------------- routing ----------------
__global__ void zero_kernel() {
    int i = threadIdx.x;
    if (i < TE) { g_counts[i] = 0; g_fill[i] = 0; }
}

__global__ void router_kernel(const float* __restrict__ x, const float* __restrict__ Wr) {
    int gw   = (int)((blockIdx.x * blockDim.x + threadIdx.x) >> 5);
    int lane = threadIdx.x & 31;
    if (gw >= TT) return;
    const float* xr = x + (size_t)gw * TD;
    float a0 = 0.f, a1 = 0.f, a2 = 0.f, a3 = 0.f;
    for (int d = lane; d < TD; d += 32) {
        float xv = xr[d];
        float4 w = *(const float4*)(Wr + d * 4);
        a0 += xv * w.x; a1 += xv * w.y; a2 += xv * w.z; a3 += xv * w.w;
    }
    #pragma unroll
    for (int o = 16; o; o >>= 1) {
        a0 += __shfl_xor_sync(0xffffffffu, a0, o);
        a1 += __shfl_xor_sync(0xffffffffu, a1, o);
        a2 += __shfl_xor_sync(0xffffffffu, a2, o);
        a3 += __shfl_xor_sync(0xffffffffu, a3, o);
    }
    if (lane == 0) {
        float l[4] = {a0, a1, a2, a3};
        float m = fmaxf(fmaxf(l[0], l[1]), fmaxf(l[2], l[3]));
        float p[4]; float s = 0.f;
        #pragma unroll
        for (int i = 0; i < 4; i++) { p[i] = __expf(l[i] - m); s += p[i]; }
        float inv = 1.0f / s;
        int i0 = 0;
        #pragma unroll
        for (int i = 1; i < 4; i++) if (p[i] > p[i0]) i0 = i;
        int i1 = (i0 == 0) ? 1 : 0;
        #pragma unroll
        for (int i = 0; i < 4; i++) if (i != i0 && p[i] > p[i1]) i1 = i;
        g_eidx[gw * 2]     = i0; g_gate[gw * 2]     = p[i0] * inv;
        g_eidx[gw * 2 + 1] = i1; g_gate[gw * 2 + 1] = p[i1] * inv;
        atomicAdd(&g_counts[i0], 1);
        atomicAdd(&g_counts[i1], 1);
    }
}

__global__ void offsets_kernel() {
    if (threadIdx.x == 0) {
        int s = 0;
        for (int e = 0; e < TE; e++) { g_offs[e] = s; s += g_counts[e]; }
        g_offs[TE] = s;
    }
}

__global__ void scatter_kernel() {
    int a = blockIdx.x * blockDim.x + threadIdx.x;
    if (a >= NA) return;
    int e = g_eidx[a];
    int pos = g_offs[e] + atomicAdd(&g_fill[e], 1);
    g_rowmap[pos]  = a;
    g_rowgate[pos] = g_gate[a];
}

// ---------------- prep: fp32 -> fp16 (x + Wg + Wu) ----------------
__global__ void cvt_xgu_kernel(const float4* __restrict__ x, const float4* __restrict__ Wg,
                               const float4* __restrict__ Wu) {
    size_t i = (size_t)blockIdx.x * blockDim.x + threadIdx.x;
    const float4* s;
    uint2* d;
    if (i < NX4) { s = x + i; d = (uint2*)g_Xh + i; }
    else if (i < NX4 + (size_t)NW4)     { size_t j = i - NX4;               s = Wg + j; d = (uint2*)g_Wgh + j; }
    else if (i < NX4 + 2 * (size_t)NW4) { size_t j = i - NX4 - (size_t)NW4; s = Wu + j; d = (uint2*)g_Wuh + j; }
    else return;
    float4 v = *s;
    uint2 o;
    o.x = packh2(v.x, v.y);
    o.y = packh2(v.z, v.w);
    *d = o;
}

// ---------------- GEMM1 + fused Wd conversion ----------------
// GEMM path (blockIdx.y < 128): H = silu(Xe*Wg) * (Xe*Wu), fp16 m16n8k16,
//   CTA tile M=128 x N=64 (G and U), 8 warps (4m x 2n), warp tile 32x32 each.
// CVT path (blockIdx.y >= 128): grid-stride fp32->fp16 of Wd into g_Wdh,
//   overlapping the compute-bound GEMM CTAs (rides idle DRAM bandwidth).
__global__ __launch_bounds__(256, 2) void gemm1_kernel(const float4* __restrict__ Wd) {
    // ---- fused Wd conversion blocks ----
    if (blockIdx.y >= TF / 64) {
        const int cid = blockIdx.x + 16 * ((blockIdx.y - TF / 64) + G1_NYC * blockIdx.z); // 0..255
        const size_t stride = (size_t)256 * G1_NYC * 16 * TE;  // 65536 threads
        for (size_t i = (size_t)cid * 256 + threadIdx.x; i < (size_t)NW4; i += stride) {
            float4 v = Wd[i];
            uint2 o;
            o.x = packh2(v.x, v.y);
            o.y = packh2(v.z, v.w);
            ((uint2*)g_Wdh)[i] = o;
        }
        return;
    }

    const int e    = blockIdx.z;
    const int cnt  = g_counts[e];
    const int row0 = blockIdx.x * 128;
    if (row0 >= cnt) return;
    const int seg = g_offs[e];
    const int f0  = blockIdx.y * 64;

    extern __shared__ __half sm[];
    int* rid = (int*)(sm + G1_STGH * NSTG);

    const int tid = threadIdx.x, lane = tid & 31, warp = tid >> 5;
    const int grp = lane >> 2, t4 = lane & 3;

    if (tid < 128) {
        int r = row0 + tid;
        rid[tid] = (r < cnt) ? (g_rowmap[seg + r] >> 1) : -1;
    }
    __syncthreads();

    // loaders
    const int arow = tid >> 1, ach = (tid & 1);        // A: 2 x 16B
    const int tok  = rid[arow];
    const uint32_t aval = (tok >= 0) ? 16u : 0u;
    const __half* aptr = g_Xh + (size_t)(tok < 0 ? 0 : tok) * TD + ach * 16;
    const int krow = tid >> 3, nc = tid & 7;           // G/U: 1 x 16B each
    const __half* gptr = g_Wgh + ((size_t)e * TD + krow) * TF + f0 + nc * 8;
    const __half* uptr = g_Wuh + ((size_t)e * TD + krow) * TF + f0 + nc * 8;

    const uint32_t smb = smem_u32(sm);
    const uint32_t aoff = smb + arow * 80 + ach * 32;
    const uint32_t goff = smb + G1_GB * 2 + krow * 144 + nc * 16;
    const uint32_t uoff = smb + G1_UB * 2 + krow * 144 + nc * 16;
    const uint32_t SSB = G1_STGH * 2;

    #pragma unroll
    for (int s = 0; s < NSTG - 1; s++) {
        int kb = s * KC;
        cpa16(aoff + s * SSB,      aptr + kb,     aval);
        cpa16(aoff + s * SSB + 16, aptr + kb + 8, aval);
        cpa16(goff + s * SSB, gptr + (size_t)kb * TF, 16u);
        cpa16(uoff + s * SSB, uptr + (size_t)kb * TF, 16u);
        cpa_commit();
    }

    float accG[2][4][4], accU[2][4][4];
    #pragma unroll
    for (int i = 0; i < 2; i++)
        #pragma unroll
        for (int j = 0; j < 4; j++)
            #pragma unroll
            for (int q = 0; q < 4; q++) { accG[i][j][q] = 0.f; accU[i][j][q] = 0.f; }

    // ldmatrix lane maps
    const int mrow0 = (warp & 3) * 32;
    const int ncol0 = (warp >> 2) * 32;
    const int aR = mrow0 + ((lane >> 3) & 1) * 8 + (lane & 7);   // + mi*16
    const int aC = (lane >> 4) * 8;                              // + ks*16
    const int bR = ((lane >> 3) & 1) * 8 + (lane & 7);           // + ks*16 (k dir)
    const int bC = ncol0 + (lane >> 4) * 8;                      // + pair*16

    const int NC = TD / KC;   // 64
    #pragma unroll 1
    for (int i = 0; i < NC; i++) {
        cpa_wait2();
        __syncthreads();
        {
            int s = (i + NSTG - 1) & 3;
            int kb = (i + NSTG - 1) * KC;
            if (kb < TD) {
                cpa16(aoff + s * SSB,      aptr + kb,     aval);
                cpa16(aoff + s * SSB + 16, aptr + kb + 8, aval);
                cpa16(goff + s * SSB, gptr + (size_t)kb * TF, 16u);
                cpa16(uoff + s * SSB, uptr + (size_t)kb * TF, 16u);
            }
            cpa_commit();
        }
        const uint32_t sbase = smb + (i & 3) * SSB;
        #pragma unroll
        for (int ks = 0; ks < 2; ks++) {
            uint32_t a[2][4];
            #pragma unroll
            for (int mi = 0; mi < 2; mi++)
                ldmx4(a[mi], sbase + (aR + mi * 16) * 80 + (aC + ks * 16) * 2);
            uint32_t bg[2][4], bu[2][4];
            #pragma unroll
            for (int p = 0; p < 2; p++) {
                uint32_t ro = (bR + ks * 16) * 144 + (bC + p * 16) * 2;
                ldmx4t(bg[p], sbase + G1_GB * 2 + ro);
                ldmx4t(bu[p], sbase + G1_UB * 2 + ro);
            }
            #pragma unroll
            for (int p = 0; p < 2; p++)
                #pragma unroll
                for (int sub = 0; sub < 2; sub++) {
                    const int ni = p * 2 + sub;
                    #pragma unroll
                    for (int mi = 0; mi < 2; mi++) {
                        mma_f16(accG[mi][ni], a[mi], bg[p][sub * 2], bg[p][sub * 2 + 1]);
                        mma_f16(accU[mi][ni], a[mi], bu[p][sub * 2], bu[p][sub * 2 + 1]);
                    }
                }
        }
    }

    // epilogue: h = silu(g)*u -> g_Hh (fp16)
    #pragma unroll
    for (int mi = 0; mi < 2; mi++) {
        const int rl = (warp & 3) * 32 + mi * 16 + grp;
        const int r0 = row0 + rl, r1 = row0 + rl + 8;
        #pragma unroll
        for (int ni = 0; ni < 4; ni++) {
            const int col = f0 + (warp >> 2) * 32 + ni * 8 + t4 * 2;
            if (r0 < cnt) {
                float gg0 = accG[mi][ni][0], uu0 = accU[mi][ni][0];
                float gg1 = accG[mi][ni][1], uu1 = accU[mi][ni][1];
                float h0 = __fdividef(gg0 * uu0, 1.0f + __expf(-gg0));
                float h1 = __fdividef(gg1 * uu1, 1.0f + __expf(-gg1));
                *(__half2*)&g_Hh[(size_t)(seg + r0) * TF + col] = __floats2half2_rn(h0, h1);
            }
            if (r1 < cnt) {
                float gg0 = accG[mi][ni][2], uu0 = accU[mi][ni][2];
                float gg1 = accG[mi][ni][3], uu1 = accU[mi][ni][3];
                float h0 = __fdividef(gg0 * uu0, 1.0f + __expf(-gg0));
                float h1 = __fdividef(gg1 * uu1, 1.0f + __expf(-gg1));
                *(__half2*)&g_Hh[(size_t)(seg + r1) * TF + col] = __floats2half2_rn(h0, h1);
            }
        }
    }
}

// ---------------- GEMM2: Y = gate * (H * Wd)  [fp16 m16n8k16, split-K x2] ----------------
// CTA tile: M=128 x N=128, K half = 4096. 8 warps (4m x 2n), warp tile 32x64.
// blockIdx.y encodes (n-panel, kslice): y = npanel*2 + kslice.
__global__ __launch_bounds__(256, 2) void gemm2_kernel() {
    const int e    = blockIdx.z;
    const int cnt  = g_counts[e];
    const int row0 = blockIdx.x * 128;
    if (row0 >= cnt) return;
    const int seg = g_offs[e];
    const int n0  = (blockIdx.y >> 1) * 128;
    const int ksl = blockIdx.y & 1;
    const int k0  = ksl * (TF / 2);
    float* Yout = ksl ? g_Y1 : g_Y0;

    extern __shared__ __half sm[];
    const int tid = threadIdx.x, lane = tid & 31, warp = tid >> 5;
    const int grp = lane >> 2, t4 = lane & 3;

    const int arow = tid >> 1, ach = (tid & 1);
    const uint32_t aval = (row0 + arow < cnt) ? 16u : 0u;
    const __half* aptr = g_Hh + (size_t)(seg + ((row0 + arow < cnt) ? row0 + arow : 0)) * TF + k0 + ach * 16;
    const int krow = tid >> 3, nc = tid & 7;
    const __half* bptr = g_Wdh + ((size_t)e * TF + k0 + krow) * TD + n0 + nc * 8;

    const uint32_t smb = smem_u32(sm);
    const uint32_t aoff = smb + arow * 80 + ach * 32;
    const uint32_t b0off = smb + G2_B0 * 2 + krow * 144 + nc * 16;
    const uint32_t b1off = smb + G2_B1 * 2 + krow * 144 + nc * 16;
    const uint32_t SSB = G2_STGH * 2;

    #pragma unroll
    for (int s = 0; s < NSTG - 1; s++) {
        int kb = s * KC;
        cpa16(aoff + s * SSB,      aptr + kb,     aval);
        cpa16(aoff + s * SSB + 16, aptr + kb + 8, aval);
        cpa16(b0off + s * SSB, bptr + (size_t)kb * TD,      16u);
        cpa16(b1off + s * SSB, bptr + (size_t)kb * TD + 64, 16u);
        cpa_commit();
    }

    float acc[2][8][4];
    #pragma unroll
    for (int i = 0; i < 2; i++)
        #pragma unroll
        for (int j = 0; j < 8; j++)
            #pragma unroll
            for (int q = 0; q < 4; q++) acc[i][j][q] = 0.f;

    const int mrow0 = (warp & 3) * 32;
    const uint32_t sBbase = (warp >> 2) ? (G2_B1 * 2) : (G2_B0 * 2);  // warp n-half
    const int aR = mrow0 + ((lane >> 3) & 1) * 8 + (lane & 7);
    const int aC = (lane >> 4) * 8;
    const int bR = ((lane >> 3) & 1) * 8 + (lane & 7);
    const int bC = (lane >> 4) * 8;                                   // + pair*16 (within 64)

    const int NC = (TF / 2) / KC;   // 128
    #pragma unroll 1
    for (int i = 0; i < NC; i++) {
        cpa_wait2();
        __syncthreads();
        {
            int s = (i + NSTG - 1) & 3;
            int kb = (i + NSTG - 1) * KC;
            if (kb < TF / 2) {
                cpa16(aoff + s * SSB,      aptr + kb,     aval);
                cpa16(aoff + s * SSB + 16, aptr + kb + 8, aval);
                cpa16(b0off + s * SSB, bptr + (size_t)kb * TD,      16u);
                cpa16(b1off + s * SSB, bptr + (size_t)kb * TD + 64, 16u);
            }
            cpa_commit();
        }
        const uint32_t sbase = smb + (i & 3) * SSB;
        #pragma unroll
        for (int ks = 0; ks < 2; ks++) {
            uint32_t a[2][4];
            #pragma unroll
            for (int mi = 0; mi < 2; mi++)
                ldmx4(a[mi], sbase + (aR + mi * 16) * 80 + (aC + ks * 16) * 2);
            #pragma unroll
            for (int p = 0; p < 4; p++) {
                uint32_t bb[4];
                ldmx4t(bb, sbase + sBbase + (bR + ks * 16) * 144 + (bC + p * 16) * 2);
                #pragma unroll
                for (int sub = 0; sub < 2; sub++) {
                    const int ni = p * 2 + sub;
                    #pragma unroll
                    for (int mi = 0; mi < 2; mi++)
                        mma_f16(acc[mi][ni], a[mi], bb[sub * 2], bb[sub * 2 + 1]);
                }
            }
        }
    }

    // epilogue: scale by gate, scatter to assignment slot (fp32)
    #pragma unroll
    for (int mi = 0; mi < 2; mi++) {
        const int rl = (warp & 3) * 32 + mi * 16 + grp;
        const int r0 = row0 + rl, r1 = row0 + rl + 8;
        int a0i = 0, a1i = 0; float w0 = 0.f, w1 = 0.f;
        if (r0 < cnt) { a0i = g_rowmap[seg + r0]; w0 = g_rowgate[seg + r0]; }
        if (r1 < cnt) { a1i = g_rowmap[seg + r1]; w1 = g_rowgate[seg + r1]; }
        #pragma unroll
        for (int ni = 0; ni < 8; ni++) {
            const int col = n0 + (warp >> 2) * 64 + ni * 8 + t4 * 2;
            if (r0 < cnt) {
                float2 v; v.x = w0 * acc[mi][ni][0]; v.y = w0 * acc[mi][ni][1];
                *(float2*)&Yout[(size_t)a0i * TD + col] = v;
            }
            if (r1 < cnt) {
                float2 v; v.x = w1 * acc[mi][ni][2]; v.y = w1 * acc[mi][ni][3];
                *(float2*)&Yout[(size_t)a1i * TD + col] = v;
            }
        }
    }
}

// ---------------- combine: out[t] = sum over 2 slots x 2 k-slices ----------------
__global__ void combine_kernel(float* __restrict__ out) {
    int i = blockIdx.x * blockDim.x + threadIdx.x;
    if (i >= TT * TD) return;
    int t = i >> 11;
    int d = i & (TD - 1);
    size_t i0 = (size_t)(2 * t) * TD + d;
    size_t i1 = (size_t)(2 * t + 1) * TD + d;
    out[i] = (g_Y0[i0] + g_Y1[i0]) + (g_Y0[i1] + g_Y1[i1]);
}

// ---------------- launch ----------------
extern "C" void kernel_launch(void* const* d_in, const int* in_sizes, int n_in,
                              void* d_out, int out_size) {
    const float* x  = (const float*)d_in[0];
    const float* Wr = (const float*)d_in[1];
    const float* Wg = (const float*)d_in[2];
    const float* Wu = (const float*)d_in[3];
    const float* Wd = (const float*)d_in[4];
    float* out = (float*)d_out;

    static int attr_done = 0;
    if (!attr_done) {
        cudaFuncSetAttribute(gemm1_kernel, cudaFuncAttributeMaxDynamicSharedMemorySize, G1_SMEM);
        cudaFuncSetAttribute(gemm2_kernel, cudaFuncAttributeMaxDynamicSharedMemorySize, G2_SMEM);
        attr_done = 1;
    }

    zero_kernel<<<1, 32>>>();
    router_kernel<<<TT / 8, 256>>>(x, Wr);
    offsets_kernel<<<1, 1>>>();
    scatter_kernel<<<NA / 256, 256>>>();

    {
        size_t total = (size_t)NX4 + 2 * (size_t)NW4;
        cvt_xgu_kernel<<<(unsigned)((total + 255) / 256), 256>>>(
            (const float4*)x, (const float4*)Wg, (const float4*)Wu);
    }

    // gemm1 + fused Wd conversion (extra grid.y panels)
    gemm1_kernel<<<dim3(16, TF / 64 + G1_NYC, TE), 256, G1_SMEM>>>((const float4*)Wd);
    gemm2_kernel<<<dim3(16, (TD / 128) * 2, TE), 256, G2_SMEM>>>();

    combine_kernel<<<(TT * TD) / 256, 256>>>(out);
}

// round 12
// speedup vs baseline: 1.4623x; 1.0002x over previous
#include <cuda_runtime.h>
#include <cuda_fp16.h>
#include <cstdint>

// Problem constants: B=2, S=1024, D=2048, F=8192, E=4, K=2
#define TT 2048
#define TD 2048
#define TF 8192
#define TE 4
#define NA 4096

#define KC 32           // K per stage (fp16)
#define NSTG 4

// GEMM1 smem (halfs/stage): A[128][40] + G[32][72] + U[32][72]
#define G1_STGH (128*40 + 32*72 + 32*72)    // 9728 halfs = 19456 B
#define G1_GB (128*40)                      // 5120
#define G1_UB (128*40 + 32*72)              // 7424
#define G1_SMEM (G1_STGH*NSTG*2 + 512)

// GEMM2 smem (halfs/stage): A[128][40] + B0[32][72] + B1[32][72]
#define G2_STGH G1_STGH
#define G2_B0 (128*40)
#define G2_B1 (128*40 + 32*72)
#define G2_SMEM (G2_STGH*NSTG*2)

#define NX4 (TT*TD/4)
#define NW4 (TE*TD*TF/4)        // float4 count per full weight tensor
#define NWH4 (NW4/2)            // float4 count per half (in f) of Wg or Wu

// gemm1 grid.y per pass: 64 GEMM panels + 4 cvt panels (16*4*4 = 256 cvt CTAs)
#define G1_NYP 64
#define G1_NYC 4

// ---------------- device scratch ----------------
__device__ int    g_counts[TE];
__device__ int    g_fill[TE];
__device__ int    g_offs[TE + 1];
__device__ int    g_eidx[NA];
__device__ float  g_gate[NA];
__device__ int    g_rowmap[NA];
__device__ float  g_rowgate[NA];
__device__ __half g_Xh[(size_t)TT * TD];
__device__ __half g_Wgh[(size_t)TE * TD * TF];
__device__ __half g_Wuh[(size_t)TE * TD * TF];
__device__ __half g_Wdh[(size_t)TE * TF * TD];
__device__ __half g_Hh[(size_t)NA * TF];
__device__ float  g_Y0[(size_t)NA * TD];    // split-K slice 0
__device__ float  g_Y1[(size_t)NA * TD];    // split-K slice 1

// ---------------- helpers ----------------
__device__ __forceinline__ uint32_t smem_u32(const void* p) {
    uint32_t a;
    asm("{ .reg .u64 t; cvta.to.shared.u64 t, %1; cvt.u32.u64 %0, t; }" : "=r"(a) : "l"(p));
    return a;
}
__device__ __forceinline__ void cpa16(uint32_t dst, const void* src, uint32_t valid) {
    asm volatile("cp.async.cg.shared.global [%0], [%1], 16, %2;" :: "r"(dst), "l"(src), "r"(valid) : "memory");
}
__device__ __forceinline__ void cpa_commit() { asm volatile("cp.async.commit_group;" ::: "memory"); }
__device__ __forceinline__ void cpa_wait2()  { asm volatile("cp.async.wait_group 2;" ::: "memory"); }

__device__ __forceinline__ void ldmx4(uint32_t* r, uint32_t addr) {
    asm volatile("ldmatrix.sync.aligned.m8n8.x4.shared.b16 {%0,%1,%2,%3}, [%4];"
                 : "=r"(r[0]), "=r"(r[1]), "=r"(r[2]), "=r"(r[3]) : "r"(addr));
}
__device__ __forceinline__ void ldmx4t(uint32_t* r, uint32_t addr) {
    asm volatile("ldmatrix.sync.aligned.m8n8.x4.trans.shared.b16 {%0,%1,%2,%3}, [%4];"
                 : "=r"(r[0]), "=r"(r[1]), "=r"(r[2]), "=r"(r[3]) : "r"(addr));
}
__device__ __forceinline__ void mma_f16(float* c, const uint32_t* a, uint32_t b0, uint32_t b1) {
    asm volatile(
        "mma.sync.aligned.m16n8k16.row.col.f32.f16.f16.f32 "
        "{%0,%1,%2,%3}, {%4,%5,%6,%7}, {%8,%9}, {%0,%1,%2,%3};"
        : "+f"(c[0]), "+f"(c[1]), "+f"(c[2]), "+f"(c[3])
        : "r"(a[0]), "r"(a[1]), "r"(a[2]), "r"(a[3]), "r"(b0), "r"(b1));
}
__device__ __forceinline__ uint32_t packh2(float a, float b) {
    __half2 h = __floats2half2_rn(a, b);
    return *(uint32_t*)&h;
}

// ---------------- routing ----------------
__global__ void zero_kernel() {
    int i = threadIdx.x;
    if (i < TE) { g_counts[i] = 0; g_fill[i] = 0; }
}

__global__ void router_kernel(const float* __restrict__ x, const float* __restrict__ Wr) {
    int gw   = (int)((blockIdx.x * blockDim.x + threadIdx.x) >> 5);
    int lane = threadIdx.x & 31;
    if (gw >= TT) return;
    const float* xr = x + (size_t)gw * TD;
    float a0 = 0.f, a1 = 0.f, a2 = 0.f, a3 = 0.f;
    for (int d = lane; d < TD; d += 32) {
        float xv = xr[d];
        float4 w = *(const float4*)(Wr + d * 4);
        a0 += xv * w.x; a1 += xv * w.y; a2 += xv * w.z; a3 += xv * w.w;
    }
    #pragma unroll
    for (int o = 16; o; o >>= 1) {
        a0 += __shfl_xor_sync(0xffffffffu, a0, o);
        a1 += __shfl_xor_sync(0xffffffffu, a1, o);
        a2 += __shfl_xor_sync(0xffffffffu, a2, o);
        a3 += __shfl_xor_sync(0xffffffffu, a3, o);
    }
    if (lane == 0) {
        float l[4] = {a0, a1, a2, a3};
        float m = fmaxf(fmaxf(l[0], l[1]), fmaxf(l[2], l[3]));
        float p[4]; float s = 0.f;
        #pragma unroll
        for (int i = 0; i < 4; i++) { p[i] = __expf(l[i] - m); s += p[i]; }
        float inv = 1.0f / s;
        int i0 = 0;
        #pragma unroll
        for (int i = 1; i < 4; i++) if (p[i] > p[i0]) i0 = i;
        int i1 = (i0 == 0) ? 1 : 0;
        #pragma unroll
        for (int i = 0; i < 4; i++) if (i != i0 && p[i] > p[i1]) i1 = i;
        g_eidx[gw * 2]     = i0; g_gate[gw * 2]     = p[i0] * inv;
        g_eidx[gw * 2 + 1] = i1; g_gate[gw * 2 + 1] = p[i1] * inv;
        atomicAdd(&g_counts[i0], 1);
        atomicAdd(&g_counts[i1], 1);
    }
}

__global__ void offsets_kernel() {
    if (threadIdx.x == 0) {
        int s = 0;
        for (int e = 0; e < TE; e++) { g_offs[e] = s; s += g_counts[e]; }
        g_offs[TE] = s;
    }
}

__global__ void scatter_kernel() {
    int a = blockIdx.x * blockDim.x + threadIdx.x;
    if (a >= NA) return;
    int e = g_eidx[a];
    int pos = g_offs[e] + atomicAdd(&g_fill[e], 1);
    g_rowmap[pos]  = a;
    g_rowgate[pos] = g_gate[a];
}

// ---------------- prep: fp32 -> fp16 (x + first f-halves of Wg, Wu) ----------------
// half0 of Wg/Wu: for each row (e*TD + krow), float4 cols [0, 1024) of 2048.
__global__ void cvt_head_kernel(const float4* __restrict__ x, const float4* __restrict__ Wg,
                                const float4* __restrict__ Wu) {
    size_t i = (size_t)blockIdx.x * blockDim.x + threadIdx.x;
    const float4* s;
    uint2* d;
    if (i < NX4) { s = x + i; d = (uint2*)g_Xh + i; }
    else if (i < NX4 + (size_t)NWH4) {
        size_t j = i - NX4;
        size_t row = j >> 10, col = j & 1023;          // 1024 float4 per half-row
        size_t full = (row << 11) + col;               // 2048 float4 per full row
        s = Wg + full; d = (uint2*)g_Wgh + full;
    } else if (i < NX4 + 2 * (size_t)NWH4) {
        size_t j = i - NX4 - (size_t)NWH4;
        size_t row = j >> 10, col = j & 1023;
        size_t full = (row << 11) + col;
        s = Wu + full; d = (uint2*)g_Wuh + full;
    } else return;
    float4 v = *s;
    uint2 o;
    o.x = packh2(v.x, v.y);
    o.y = packh2(v.z, v.w);
    *d = o;
}

// ---------------- GEMM1 (half-F pass) + fused conversion ----------------
// GEMM path (blockIdx.y < 64): H = silu(Xe*Wg) * (Xe*Wu) for f in [f_base, f_base+4096).
// CVT path (blockIdx.y >= 64):
//   cvt_mode 0 (pass A): convert second f-halves of Wg and Wu (needed by pass B).
//   cvt_mode 1 (pass B): convert all of Wd (needed by gemm2).
__global__ __launch_bounds__(256, 2) void gemm1_kernel(
    int f_base, int cvt_mode,
    const float4* __restrict__ Wg, const float4* __restrict__ Wu, const float4* __restrict__ Wd) {
    // ---- fused conversion blocks ----
    if (blockIdx.y >= G1_NYP) {
        const int cid = blockIdx.x + 16 * ((blockIdx.y - G1_NYP) + G1_NYC * blockIdx.z); // 0..255
        const size_t nthreads = (size_t)256 * G1_NYC * 16 * TE;  // 65536
        if (cvt_mode == 0) {
            // Wg half1 then Wu half1: 2*NWH4 elements
            for (size_t j = (size_t)cid * 256 + threadIdx.x; j < 2 * (size_t)NWH4; j += nthreads) {
                const float4* s; uint2* d;
                size_t jj = (j < (size_t)NWH4) ? j : j - (size_t)NWH4;
                size_t row = jj >> 10, col = jj & 1023;
                size_t full = (row << 11) + 1024 + col;   // second half of row
                if (j < (size_t)NWH4) { s = Wg + full; d = (uint2*)g_Wgh + full; }
                else                  { s = Wu + full; d = (uint2*)g_Wuh + full; }
                float4 v = *s;
                uint2 o;
                o.x = packh2(v.x, v.y);
                o.y = packh2(v.z, v.w);
                *d = o;
            }
        } else {
            for (size_t j = (size_t)cid * 256 + threadIdx.x; j < (size_t)NW4; j += nthreads) {
                float4 v = Wd[j];
                uint2 o;
                o.x = packh2(v.x, v.y);
                o.y = packh2(v.z, v.w);
                ((uint2*)g_Wdh)[j] = o;
            }
        }
        return;
    }

    const int e    = blockIdx.z;
    const int cnt  = g_counts[e];
    const int row0 = blockIdx.x * 128;
    if (row0 >= cnt) return;
    const int seg = g_offs[e];
    const int f0  = f_base + blockIdx.y * 64;

    extern __shared__ __half sm[];
    int* rid = (int*)(sm + G1_STGH * NSTG);

    const int tid = threadIdx.x, lane = tid & 31, warp = tid >> 5;
    const int grp = lane >> 2, t4 = lane & 3;

    if (tid < 128) {
        int r = row0 + tid;
        rid[tid] = (r < cnt) ? (g_rowmap[seg + r] >> 1) : -1;
    }
    __syncthreads();

    // loaders
    const int arow = tid >> 1, ach = (tid & 1);        // A: 2 x 16B
    const int tok  = rid[arow];
    const uint32_t aval = (tok >= 0) ? 16u : 0u;
    const __half* aptr = g_Xh + (size_t)(tok < 0 ? 0 : tok) * TD + ach * 16;
    const int krow = tid >> 3, nc = tid & 7;           // G/U: 1 x 16B each
    const __half* gptr = g_Wgh + ((size_t)e * TD + krow) * TF + f0 + nc * 8;
    const __half* uptr = g_Wuh + ((size_t)e * TD + krow) * TF + f0 + nc * 8;

    const uint32_t smb = smem_u32(sm);
    const uint32_t aoff = smb + arow * 80 + ach * 32;
    const uint32_t goff = smb + G1_GB * 2 + krow * 144 + nc * 16;
    const uint32_t uoff = smb + G1_UB * 2 + krow * 144 + nc * 16;
    const uint32_t SSB = G1_STGH * 2;

    #pragma unroll
    for (int s = 0; s < NSTG - 1; s++) {
        int kb = s * KC;
        cpa16(aoff + s * SSB,      aptr + kb,     aval);
        cpa16(aoff + s * SSB + 16, aptr + kb + 8, aval);
        cpa16(goff + s * SSB, gptr + (size_t)kb * TF, 16u);
        cpa16(uoff + s * SSB, uptr + (size_t)kb * TF, 16u);
        cpa_commit();
    }

    float accG[2][4][4], accU[2][4][4];
    #pragma unroll
    for (int i = 0; i < 2; i++)
        #pragma unroll
        for (int j = 0; j < 4; j++)
            #pragma unroll
            for (int q = 0; q < 4; q++) { accG[i][j][q] = 0.f; accU[i][j][q] = 0.f; }

    // ldmatrix lane maps
    const int mrow0 = (warp & 3) * 32;
    const int ncol0 = (warp >> 2) * 32;
    const int aR = mrow0 + ((lane >> 3) & 1) * 8 + (lane & 7);   // + mi*16
    const int aC = (lane >> 4) * 8;                              // + ks*16
    const int bR = ((lane >> 3) & 1) * 8 + (lane & 7);           // + ks*16 (k dir)
    const int bC = ncol0 + (lane >> 4) * 8;                      // + pair*16

    const int NC = TD / KC;   // 64
    #pragma unroll 1
    for (int i = 0; i < NC; i++) {
        cpa_wait2();
        __syncthreads();
        {
            int s = (i + NSTG - 1) & 3;
            int kb = (i + NSTG - 1) * KC;
            if (kb < TD) {
                cpa16(aoff + s * SSB,      aptr + kb,     aval);
                cpa16(aoff + s * SSB + 16, aptr + kb + 8, aval);
                cpa16(goff + s * SSB, gptr + (size_t)kb * TF, 16u);
                cpa16(uoff + s * SSB, uptr + (size_t)kb * TF, 16u);
            }
            cpa_commit();
        }
        const uint32_t sbase = smb + (i & 3) * SSB;
        #pragma unroll
        for (int ks = 0; ks < 2; ks++) {
            uint32_t a[2][4];
            #pragma unroll
            for (int mi = 0; mi < 2; mi++)
                ldmx4(a[mi], sbase + (aR + mi * 16) * 80 + (aC + ks * 16) * 2);
            uint32_t bg[2][4], bu[2][4];
            #pragma unroll
            for (int p = 0; p < 2; p++) {
                uint32_t ro = (bR + ks * 16) * 144 + (bC + p * 16) * 2;
                ldmx4t(bg[p], sbase + G1_GB * 2 + ro);
                ldmx4t(bu[p], sbase + G1_UB * 2 + ro);
            }
            #pragma unroll
            for (int p = 0; p < 2; p++)
                #pragma unroll
                for (int sub = 0; sub < 2; sub++) {
                    const int ni = p * 2 + sub;
                    #pragma unroll
                    for (int mi = 0; mi < 2; mi++) {
                        mma_f16(accG[mi][ni], a[mi], bg[p][sub * 2], bg[p][sub * 2 + 1]);
                        mma_f16(accU[mi][ni], a[mi], bu[p][sub * 2], bu[p][sub * 2 + 1]);
                    }
                }
        }
    }

    // epilogue: h = silu(g)*u -> g_Hh (fp16)
    #pragma unroll
    for (int mi = 0; mi < 2; mi++) {
        const int rl = (warp & 3) * 32 + mi * 16 + grp;
        const int r0 = row0 + rl, r1 = row0 + rl + 8;
        #pragma unroll
        for (int ni = 0; ni < 4; ni++) {
            const int col = f0 + (warp >> 2) * 32 + ni * 8 + t4 * 2;
            if (r0 < cnt) {
                float gg0 = accG[mi][ni][0], uu0 = accU[mi][ni][0];
                float gg1 = accG[mi][ni][1], uu1 = accU[mi][ni][1];
                float h0 = __fdividef(gg0 * uu0, 1.0f + __expf(-gg0));
                float h1 = __fdividef(gg1 * uu1, 1.0f + __expf(-gg1));
                *(__half2*)&g_Hh[(size_t)(seg + r0) * TF + col] = __floats2half2_rn(h0, h1);
            }
            if (r1 < cnt) {
                float gg0 = accG[mi][ni][2], uu0 = accU[mi][ni][2];
                float gg1 = accG[mi][ni][3], uu1 = accU[mi][ni][3];
                float h0 = __fdividef(gg0 * uu0, 1.0f + __expf(-gg0));
                float h1 = __fdividef(gg1 * uu1, 1.0f + __expf(-gg1));
                *(__half2*)&g_Hh[(size_t)(seg + r1) * TF + col] = __floats2half2_rn(h0, h1);
            }
        }
    }
}

// ---------------- GEMM2: Y = gate * (H * Wd)  [fp16 m16n8k16, split-K x2] ----------------
// CTA tile: M=128 x N=128, K half = 4096. 8 warps (4m x 2n), warp tile 32x64.
// blockIdx.y encodes (n-panel, kslice): y = npanel*2 + kslice.
__global__ __launch_bounds__(256, 2) void gemm2_kernel() {
    const int e    = blockIdx.z;
    const int cnt  = g_counts[e];
    const int row0 = blockIdx.x * 128;
    if (row0 >= cnt) return;
    const int seg = g_offs[e];
    const int n0  = (blockIdx.y >> 1) * 128;
    const int ksl = blockIdx.y & 1;
    const int k0  = ksl * (TF / 2);
    float* Yout = ksl ? g_Y1 : g_Y0;

    extern __shared__ __half sm[];
    const int tid = threadIdx.x, lane = tid & 31, warp = tid >> 5;
    const int grp = lane >> 2, t4 = lane & 3;

    const int arow = tid >> 1, ach = (tid & 1);
    const uint32_t aval = (row0 + arow < cnt) ? 16u : 0u;
    const __half* aptr = g_Hh + (size_t)(seg + ((row0 + arow < cnt) ? row0 + arow : 0)) * TF + k0 + ach * 16;
    const int krow = tid >> 3, nc = tid & 7;
    const __half* bptr = g_Wdh + ((size_t)e * TF + k0 + krow) * TD + n0 + nc * 8;

    const uint32_t smb = smem_u32(sm);
    const uint32_t aoff = smb + arow * 80 + ach * 32;
    const uint32_t b0off = smb + G2_B0 * 2 + krow * 144 + nc * 16;
    const uint32_t b1off = smb + G2_B1 * 2 + krow * 144 + nc * 16;
    const uint32_t SSB = G2_STGH * 2;

    #pragma unroll
    for (int s = 0; s < NSTG - 1; s++) {
        int kb = s * KC;
        cpa16(aoff + s * SSB,      aptr + kb,     aval);
        cpa16(aoff + s * SSB + 16, aptr + kb + 8, aval);
        cpa16(b0off + s * SSB, bptr + (size_t)kb * TD,      16u);
        cpa16(b1off + s * SSB, bptr + (size_t)kb * TD + 64, 16u);
        cpa_commit();
    }

    float acc[2][8][4];
    #pragma unroll
    for (int i = 0; i < 2; i++)
        #pragma unroll
        for (int j = 0; j < 8; j++)
            #pragma unroll
            for (int q = 0; q < 4; q++) acc[i][j][q] = 0.f;

    const int mrow0 = (warp & 3) * 32;
    const uint32_t sBbase = (warp >> 2) ? (G2_B1 * 2) : (G2_B0 * 2);  // warp n-half
    const int aR = mrow0 + ((lane >> 3) & 1) * 8 + (lane & 7);
    const int aC = (lane >> 4) * 8;
    const int bR = ((lane >> 3) & 1) * 8 + (lane & 7);
    const int bC = (lane >> 4) * 8;                                   // + pair*16 (within 64)

    const int NC = (TF / 2) / KC;   // 128
    #pragma unroll 1
    for (int i = 0; i < NC; i++) {
        cpa_wait2();
        __syncthreads();
        {
            int s = (i + NSTG - 1) & 3;
            int kb = (i + NSTG - 1) * KC;
            if (kb < TF / 2) {
                cpa16(aoff + s * SSB,      aptr + kb,     aval);
                cpa16(aoff + s * SSB + 16, aptr + kb + 8, aval);
                cpa16(b0off + s * SSB, bptr + (size_t)kb * TD,      16u);
                cpa16(b1off + s * SSB, bptr + (size_t)kb * TD + 64, 16u);
            }
            cpa_commit();
        }
        const uint32_t sbase = smb + (i & 3) * SSB;
        #pragma unroll
        for (int ks = 0; ks < 2; ks++) {
            uint32_t a[2][4];
            #pragma unroll
            for (int mi = 0; mi < 2; mi++)
                ldmx4(a[mi], sbase + (aR + mi * 16) * 80 + (aC + ks * 16) * 2);
            #pragma unroll
            for (int p = 0; p < 4; p++) {
                uint32_t bb[4];
                ldmx4t(bb, sbase + sBbase + (bR + ks * 16) * 144 + (bC + p * 16) * 2);
                #pragma unroll
                for (int sub = 0; sub < 2; sub++) {
                    const int ni = p * 2 + sub;
                    #pragma unroll
                    for (int mi = 0; mi < 2; mi++)
                        mma_f16(acc[mi][ni], a[mi], bb[sub * 2], bb[sub * 2 + 1]);
                }
            }
        }
    }

    // epilogue: scale by gate, scatter to assignment slot (fp32)
    #pragma unroll
    for (int mi = 0; mi < 2; mi++) {
        const int rl = (warp & 3) * 32 + mi * 16 + grp;
        const int r0 = row0 + rl, r1 = row0 + rl + 8;
        int a0i = 0, a1i = 0; float w0 = 0.f, w1 = 0.f;
        if (r0 < cnt) { a0i = g_rowmap[seg + r0]; w0 = g_rowgate[seg + r0]; }
        if (r1 < cnt) { a1i = g_rowmap[seg + r1]; w1 = g_rowgate[seg + r1]; }
        #pragma unroll
        for (int ni = 0; ni < 8; ni++) {
            const int col = n0 + (warp >> 2) * 64 + ni * 8 + t4 * 2;
            if (r0 < cnt) {
                float2 v; v.x = w0 * acc[mi][ni][0]; v.y = w0 * acc[mi][ni][1];
                *(float2*)&Yout[(size_t)a0i * TD + col] = v;
            }
            if (r1 < cnt) {
                float2 v; v.x = w1 * acc[mi][ni][2]; v.y = w1 * acc[mi][ni][3];
                *(float2*)&Yout[(size_t)a1i * TD + col] = v;
            }
        }
    }
}

// ---------------- combine: out[t] = sum over 2 slots x 2 k-slices ----------------
__global__ void combine_kernel(float* __restrict__ out) {
    int i = blockIdx.x * blockDim.x + threadIdx.x;
    if (i >= TT * TD) return;
    int t = i >> 11;
    int d = i & (TD - 1);
    size_t i0 = (size_t)(2 * t) * TD + d;
    size_t i1 = (size_t)(2 * t + 1) * TD + d;
    out[i] = (g_Y0[i0] + g_Y1[i0]) + (g_Y0[i1] + g_Y1[i1]);
}

// ---------------- launch ----------------
extern "C" void kernel_launch(void* const* d_in, const int* in_sizes, int n_in,
                              void* d_out, int out_size) {
    const float* x  = (const float*)d_in[0];
    const float* Wr = (const float*)d_in[1];
    const float* Wg = (const float*)d_in[2];
    const float* Wu = (const float*)d_in[3];
    const float* Wd = (const float*)d_in[4];
    float* out = (float*)d_out;

    static int attr_done = 0;
    if (!attr_done) {
        cudaFuncSetAttribute(gemm1_kernel, cudaFuncAttributeMaxDynamicSharedMemorySize, G1_SMEM);
        cudaFuncSetAttribute(gemm2_kernel, cudaFuncAttributeMaxDynamicSharedMemorySize, G2_SMEM);
        attr_done = 1;
    }

    zero_kernel<<<1, 32>>>();
    router_kernel<<<TT / 8, 256>>>(x, Wr);
    offsets_kernel<<<1, 1>>>();
    scatter_kernel<<<NA / 256, 256>>>();

    // serial prep: x + first f-halves of Wg/Wu
    {
        size_t total = (size_t)NX4 + 2 * (size_t)NWH4;
        cvt_head_kernel<<<(unsigned)((total + 255) / 256), 256>>>(
            (const float4*)x, (const float4*)Wg, (const float4*)Wu);
    }

    // pass A: GEMM f [0,4096) + fused cvt of Wg/Wu second halves
    gemm1_kernel<<<dim3(16, G1_NYP + G1_NYC, TE), 256, G1_SMEM>>>(
        0, 0, (const float4*)Wg, (const float4*)Wu, (const float4*)Wd);
    // pass B: GEMM f [4096,8192) + fused cvt of Wd
    gemm1_kernel<<<dim3(16, G1_NYP + G1_NYC, TE), 256, G1_SMEM>>>(
        TF / 2, 1, (const float4*)Wg, (const float4*)Wu, (const float4*)Wd);

    gemm2_kernel<<<dim3(16, (TD / 128) * 2, TE), 256, G2_SMEM>>>();

    combine_kernel<<<(TT * TD) / 256, 256>>>(out);
}

// round 14
// speedup vs baseline: 1.4804x; 1.0124x over previous
#include <cuda_runtime.h>
#include <cuda_fp16.h>
#include <cstdint>

// Problem constants: B=2, S=1024, D=2048, F=8192, E=4, K=2
#define TT 2048
#define TD 2048
#define TF 8192
#define TE 4
#define NA 4096

#define KC 32           // K per stage (fp16)
#define NSTG 4

// GEMM1 smem (halfs/stage): A[128][40] + G[32][72] + U[32][72]
#define G1_STGH (128*40 + 32*72 + 32*72)    // 9728 halfs = 19456 B
#define G1_GB (128*40)                      // 5120
#define G1_UB (128*40 + 32*72)              // 7424
#define G1_SMEM (G1_STGH*NSTG*2 + 512)

// GEMM2 smem (halfs/stage): A[128][40] + B0[32][72] + B1[32][72]
#define G2_STGH G1_STGH
#define G2_B0 (128*40)
#define G2_B1 (128*40 + 32*72)
#define G2_SMEM (G2_STGH*NSTG*2)

#define NX4 (TT*TD/4)
#define NW4 (TE*TD*TF/4)        // float4 count per full weight tensor
#define NWH4 (NW4/2)            // float4 count per half (in f) of Wg or Wu

// gemm1 grid.y per pass: 64 GEMM panels + 4 cvt panels (16*4*4 = 256 cvt CTAs)
#define G1_NYP 64
#define G1_NYC 4

// prep kernel: 256 router blocks + 8192 cvt blocks
#define PREP_NRB 256
#define PREP_NCB 8192

// ---------------- device scratch ----------------
__device__ int    g_counts[TE];
__device__ int    g_fill[TE];
__device__ int    g_offs[TE + 1];
__device__ int    g_eidx[NA];
__device__ float  g_gate[NA];
__device__ int    g_rowmap[NA];
__device__ float  g_rowgate[NA];
__device__ __half g_Xh[(size_t)TT * TD];
__device__ __half g_Wgh[(size_t)TE * TD * TF];
__device__ __half g_Wuh[(size_t)TE * TD * TF];
__device__ __half g_Wdh[(size_t)TE * TF * TD];
__device__ __half g_Hh[(size_t)NA * TF];
__device__ __half g_Y0h[(size_t)NA * TD];   // split-K slice 0 (fp16)
__device__ __half g_Y1h[(size_t)NA * TD];   // split-K slice 1 (fp16)

// ---------------- helpers ----------------
__device__ __forceinline__ uint32_t smem_u32(const void* p) {
    uint32_t a;
    asm("{ .reg .u64 t; cvta.to.shared.u64 t, %1; cvt.u32.u64 %0, t; }" : "=r"(a) : "l"(p));
    return a;
}
__device__ __forceinline__ void cpa16(uint32_t dst, const void* src, uint32_t valid) {
    asm volatile("cp.async.cg.shared.global [%0], [%1], 16, %2;" :: "r"(dst), "l"(src), "r"(valid) : "memory");
}
__device__ __forceinline__ void cpa_commit() { asm volatile("cp.async.commit_group;" ::: "memory"); }
__device__ __forceinline__ void cpa_wait2()  { asm volatile("cp.async.wait_group 2;" ::: "memory"); }

__device__ __forceinline__ void ldmx4(uint32_t* r, uint32_t addr) {
    asm volatile("ldmatrix.sync.aligned.m8n8.x4.shared.b16 {%0,%1,%2,%3}, [%4];"
                 : "=r"(r[0]), "=r"(r[1]), "=r"(r[2]), "=r"(r[3]) : "r"(addr));
}
__device__ __forceinline__ void ldmx4t(uint32_t* r, uint32_t addr) {
    asm volatile("ldmatrix.sync.aligned.m8n8.x4.trans.shared.b16 {%0,%1,%2,%3}, [%4];"
                 : "=r"(r[0]), "=r"(r[1]), "=r"(r[2]), "=r"(r[3]) : "r"(addr));
}
__device__ __forceinline__ void mma_f16(float* c, const uint32_t* a, uint32_t b0, uint32_t b1) {
    asm volatile(
        "mma.sync.aligned.m16n8k16.row.col.f32.f16.f16.f32 "
        "{%0,%1,%2,%3}, {%4,%5,%6,%7}, {%8,%9}, {%0,%1,%2,%3};"
        : "+f"(c[0]), "+f"(c[1]), "+f"(c[2]), "+f"(c[3])
        : "r"(a[0]), "r"(a[1]), "r"(a[2]), "r"(a[3]), "r"(b0), "r"(b1));
}
__device__ __forceinline__ uint32_t packh2(float a, float b) {
    __half2 h = __floats2half2_rn(a, b);
    return *(uint32_t*)&h;
}

// ---------------- prep: fused router + fp32->fp16 cvt (x, Wg/Wu first f-halves) ----------------
// blocks [0, PREP_NRB): router — one warp per token, writes g_eidx/g_gate (no atomics).
// blocks [PREP_NRB, PREP_NRB+PREP_NCB): grid-stride cvt of x + half0 of Wg and Wu.
__global__ void prep_kernel(const float* __restrict__ x, const float* __restrict__ Wr,
                            const float4* __restrict__ Wg, const float4* __restrict__ Wu) {
    if (blockIdx.x < PREP_NRB) {
        int gw   = (int)((blockIdx.x * blockDim.x + threadIdx.x) >> 5);
        int lane = threadIdx.x & 31;
        if (gw >= TT) return;
        const float* xr = x + (size_t)gw * TD;
        float a0 = 0.f, a1 = 0.f, a2 = 0.f, a3 = 0.f;
        for (int d = lane; d < TD; d += 32) {
            float xv = xr[d];
            float4 w = *(const float4*)(Wr + d * 4);
            a0 += xv * w.x; a1 += xv * w.y; a2 += xv * w.z; a3 += xv * w.w;
        }
        #pragma unroll
        for (int o = 16; o; o >>= 1) {
            a0 += __shfl_xor_sync(0xffffffffu, a0, o);
            a1 += __shfl_xor_sync(0xffffffffu, a1, o);
            a2 += __shfl_xor_sync(0xffffffffu, a2, o);
            a3 += __shfl_xor_sync(0xffffffffu, a3, o);
        }
        if (lane == 0) {
            float l[4] = {a0, a1, a2, a3};
            float m = fmaxf(fmaxf(l[0], l[1]), fmaxf(l[2], l[3]));
            float p[4]; float s = 0.f;
            #pragma unroll
            for (int i = 0; i < 4; i++) { p[i] = __expf(l[i] - m); s += p[i]; }
            float inv = 1.0f / s;
            int i0 = 0;
            #pragma unroll
            for (int i = 1; i < 4; i++) if (p[i] > p[i0]) i0 = i;
            int i1 = (i0 == 0) ? 1 : 0;
            #pragma unroll
            for (int i = 0; i < 4; i++) if (i != i0 && p[i] > p[i1]) i1 = i;
            g_eidx[gw * 2]     = i0; g_gate[gw * 2]     = p[i0] * inv;
            g_eidx[gw * 2 + 1] = i1; g_gate[gw * 2 + 1] = p[i1] * inv;
        }
        return;
    }

    // cvt path: x (NX4) + Wg half0 (NWH4) + Wu half0 (NWH4)
    const size_t total = (size_t)NX4 + 2 * (size_t)NWH4;
    const size_t stride = (size_t)PREP_NCB * 256;
    for (size_t i = (size_t)(blockIdx.x - PREP_NRB) * 256 + threadIdx.x; i < total; i += stride) {
        const float4* s;
        uint2* d;
        if (i < NX4) { s = (const float4*)x + i; d = (uint2*)g_Xh + i; }
        else if (i < NX4 + (size_t)NWH4) {
            size_t j = i - NX4;
            size_t row = j >> 10, col = j & 1023;          // 1024 float4 per half-row
            size_t full = (row << 11) + col;               // 2048 float4 per full row
            s = Wg + full; d = (uint2*)g_Wgh + full;
        } else {
            size_t j = i - NX4 - (size_t)NWH4;
            size_t row = j >> 10, col = j & 1023;
            size_t full = (row << 11) + col;
            s = Wu + full; d = (uint2*)g_Wuh + full;
        }
        float4 v = *s;
        uint2 o;
        o.x = packh2(v.x, v.y);
        o.y = packh2(v.z, v.w);
        *d = o;
    }
}

// ---------------- offsets: 1 CTA — counts from g_eidx, prefix, zero fill ----------------
__global__ void offsets_kernel() {
    __shared__ int cnt[TE];
    int tid = threadIdx.x;
    if (tid < TE) cnt[tid] = 0;
    __syncthreads();
    for (int i = tid; i < NA; i += 256) atomicAdd(&cnt[g_eidx[i]], 1);
    __syncthreads();
    if (tid == 0) {
        int s = 0;
        for (int e = 0; e < TE; e++) { g_counts[e] = cnt[e]; g_offs[e] = s; s += cnt[e]; }
        g_offs[TE] = s;
    }
    if (tid < TE) g_fill[tid] = 0;
}

__global__ void scatter_kernel() {
    int a = blockIdx.x * blockDim.x + threadIdx.x;
    if (a >= NA) return;
    int e = g_eidx[a];
    int pos = g_offs[e] + atomicAdd(&g_fill[e], 1);
    g_rowmap[pos]  = a;
    g_rowgate[pos] = g_gate[a];
}

// ---------------- GEMM1 (half-F pass) + fused conversion ----------------
// GEMM path (blockIdx.y < 64): H = silu(Xe*Wg) * (Xe*Wu) for f in [f_base, f_base+4096).
// CVT path (blockIdx.y >= 64):
//   cvt_mode 0 (pass A): convert second f-halves of Wg and Wu (needed by pass B).
//   cvt_mode 1 (pass B): convert all of Wd (needed by gemm2).
__global__ __launch_bounds__(256, 2) void gemm1_kernel(
    int f_base, int cvt_mode,
    const float4* __restrict__ Wg, const float4* __restrict__ Wu, const float4* __restrict__ Wd) {
    // ---- fused conversion blocks ----
    if (blockIdx.y >= G1_NYP) {
        const int cid = blockIdx.x + 16 * ((blockIdx.y - G1_NYP) + G1_NYC * blockIdx.z); // 0..255
        const size_t nthreads = (size_t)256 * G1_NYC * 16 * TE;  // 65536
        if (cvt_mode == 0) {
            for (size_t j = (size_t)cid * 256 + threadIdx.x; j < 2 * (size_t)NWH4; j += nthreads) {
                const float4* s; uint2* d;
                size_t jj = (j < (size_t)NWH4) ? j : j - (size_t)NWH4;
                size_t row = jj >> 10, col = jj & 1023;
                size_t full = (row << 11) + 1024 + col;   // second half of row
                if (j < (size_t)NWH4) { s = Wg + full; d = (uint2*)g_Wgh + full; }
                else                  { s = Wu + full; d = (uint2*)g_Wuh + full; }
                float4 v = *s;
                uint2 o;
                o.x = packh2(v.x, v.y);
                o.y = packh2(v.z, v.w);
                *d = o;
            }
        } else {
            for (size_t j = (size_t)cid * 256 + threadIdx.x; j < (size_t)NW4; j += nthreads) {
                float4 v = Wd[j];
                uint2 o;
                o.x = packh2(v.x, v.y);
                o.y = packh2(v.z, v.w);
                ((uint2*)g_Wdh)[j] = o;
            }
        }
        return;
    }

    const int e    = blockIdx.z;
    const int cnt  = g_counts[e];
    const int row0 = blockIdx.x * 128;
    if (row0 >= cnt) return;
    const int seg = g_offs[e];
    const int f0  = f_base + blockIdx.y * 64;

    extern __shared__ __half sm[];
    int* rid = (int*)(sm + G1_STGH * NSTG);

    const int tid = threadIdx.x, lane = tid & 31, warp = tid >> 5;
    const int grp = lane >> 2, t4 = lane & 3;

    if (tid < 128) {
        int r = row0 + tid;
        rid[tid] = (r < cnt) ? (g_rowmap[seg + r] >> 1) : -1;
    }
    __syncthreads();

    // loaders
    const int arow = tid >> 1, ach = (tid & 1);        // A: 2 x 16B
    const int tok  = rid[arow];
    const uint32_t aval = (tok >= 0) ? 16u : 0u;
    const __half* aptr = g_Xh + (size_t)(tok < 0 ? 0 : tok) * TD + ach * 16;
    const int krow = tid >> 3, nc = tid & 7;           // G/U: 1 x 16B each
    const __half* gptr = g_Wgh + ((size_t)e * TD + krow) * TF + f0 + nc * 8;
    const __half* uptr = g_Wuh + ((size_t)e * TD + krow) * TF + f0 + nc * 8;

    const uint32_t smb = smem_u32(sm);
    const uint32_t aoff = smb + arow * 80 + ach * 32;
    const uint32_t goff = smb + G1_GB * 2 + krow * 144 + nc * 16;
    const uint32_t uoff = smb + G1_UB * 2 + krow * 144 + nc * 16;
    const uint32_t SSB = G1_STGH * 2;

    #pragma unroll
    for (int s = 0; s < NSTG - 1; s++) {
        int kb = s * KC;
        cpa16(aoff + s * SSB,      aptr + kb,     aval);
        cpa16(aoff + s * SSB + 16, aptr + kb + 8, aval);
        cpa16(goff + s * SSB, gptr + (size_t)kb * TF, 16u);
        cpa16(uoff + s * SSB, uptr + (size_t)kb * TF, 16u);
        cpa_commit();
    }

    float accG[2][4][4], accU[2][4][4];
    #pragma unroll
    for (int i = 0; i < 2; i++)
        #pragma unroll
        for (int j = 0; j < 4; j++)
            #pragma unroll
            for (int q = 0; q < 4; q++) { accG[i][j][q] = 0.f; accU[i][j][q] = 0.f; }

    // ldmatrix lane maps
    const int mrow0 = (warp & 3) * 32;
    const int ncol0 = (warp >> 2) * 32;
    const int aR = mrow0 + ((lane >> 3) & 1) * 8 + (lane & 7);   // + mi*16
    const int aC = (lane >> 4) * 8;                              // + ks*16
    const int bR = ((lane >> 3) & 1) * 8 + (lane & 7);           // + ks*16 (k dir)
    const int bC = ncol0 + (lane >> 4) * 8;                      // + pair*16

    const int NC = TD / KC;   // 64
    #pragma unroll 1
    for (int i = 0; i < NC; i++) {
        cpa_wait2();
        __syncthreads();
        {
            int s = (i + NSTG - 1) & 3;
            int kb = (i + NSTG - 1) * KC;
            if (kb < TD) {
                cpa16(aoff + s * SSB,      aptr + kb,     aval);
                cpa16(aoff + s * SSB + 16, aptr + kb + 8, aval);
                cpa16(goff + s * SSB, gptr + (size_t)kb * TF, 16u);
                cpa16(uoff + s * SSB, uptr + (size_t)kb * TF, 16u);
            }
            cpa_commit();
        }
        const uint32_t sbase = smb + (i & 3) * SSB;
        #pragma unroll
        for (int ks = 0; ks < 2; ks++) {
            uint32_t a[2][4];
            #pragma unroll
            for (int mi = 0; mi < 2; mi++)
                ldmx4(a[mi], sbase + (aR + mi * 16) * 80 + (aC + ks * 16) * 2);
            uint32_t bg[2][4], bu[2][4];
            #pragma unroll
            for (int p = 0; p < 2; p++) {
                uint32_t ro = (bR + ks * 16) * 144 + (bC + p * 16) * 2;
                ldmx4t(bg[p], sbase + G1_GB * 2 + ro);
                ldmx4t(bu[p], sbase + G1_UB * 2 + ro);
            }
            #pragma unroll
            for (int p = 0; p < 2; p++)
                #pragma unroll
                for (int sub = 0; sub < 2; sub++) {
                    const int ni = p * 2 + sub;
                    #pragma unroll
                    for (int mi = 0; mi < 2; mi++) {
                        mma_f16(accG[mi][ni], a[mi], bg[p][sub * 2], bg[p][sub * 2 + 1]);
                        mma_f16(accU[mi][ni], a[mi], bu[p][sub * 2], bu[p][sub * 2 + 1]);
                    }
                }
        }
    }

    // epilogue: h = silu(g)*u -> g_Hh (fp16)
    #pragma unroll
    for (int mi = 0; mi < 2; mi++) {
        const int rl = (warp & 3) * 32 + mi * 16 + grp;
        const int r0 = row0 + rl, r1 = row0 + rl + 8;
        #pragma unroll
        for (int ni = 0; ni < 4; ni++) {
            const int col = f0 + (warp >> 2) * 32 + ni * 8 + t4 * 2;
            if (r0 < cnt) {
                float gg0 = accG[mi][ni][0], uu0 = accU[mi][ni][0];
                float gg1 = accG[mi][ni][1], uu1 = accU[mi][ni][1];
                float h0 = __fdividef(gg0 * uu0, 1.0f + __expf(-gg0));
                float h1 = __fdividef(gg1 * uu1, 1.0f + __expf(-gg1));
                *(__half2*)&g_Hh[(size_t)(seg + r0) * TF + col] = __floats2half2_rn(h0, h1);
            }
            if (r1 < cnt) {
                float gg0 = accG[mi][ni][2], uu0 = accU[mi][ni][2];
                float gg1 = accG[mi][ni][3], uu1 = accU[mi][ni][3];
                float h0 = __fdividef(gg0 * uu0, 1.0f + __expf(-gg0));
                float h1 = __fdividef(gg1 * uu1, 1.0f + __expf(-gg1));
                *(__half2*)&g_Hh[(size_t)(seg + r1) * TF + col] = __floats2half2_rn(h0, h1);
            }
        }
    }
}

// ---------------- GEMM2: Y = gate * (H * Wd)  [fp16 m16n8k16, split-K x2] ----------------
// CTA tile: M=128 x N=128, K half = 4096. 8 warps (4m x 2n), warp tile 32x64.
// blockIdx.y encodes (n-panel, kslice): y = npanel*2 + kslice.
__global__ __launch_bounds__(256, 2) void gemm2_kernel() {
    const int e    = blockIdx.z;
    const int cnt  = g_counts[e];
    const int row0 = blockIdx.x * 128;
    if (row0 >= cnt) return;
    const int seg = g_offs[e];
    const int n0  = (blockIdx.y >> 1) * 128;
    const int ksl = blockIdx.y & 1;
    const int k0  = ksl * (TF / 2);
    __half* Yout = ksl ? g_Y1h : g_Y0h;

    extern __shared__ __half sm[];
    const int tid = threadIdx.x, lane = tid & 31, warp = tid >> 5;
    const int grp = lane >> 2, t4 = lane & 3;

    const int arow = tid >> 1, ach = (tid & 1);
    const uint32_t aval = (row0 + arow < cnt) ? 16u : 0u;
    const __half* aptr = g_Hh + (size_t)(seg + ((row0 + arow < cnt) ? row0 + arow : 0)) * TF + k0 + ach * 16;
    const int krow = tid >> 3, nc = tid & 7;
    const __half* bptr = g_Wdh + ((size_t)e * TF + k0 + krow) * TD + n0 + nc * 8;

    const uint32_t smb = smem_u32(sm);
    const uint32_t aoff = smb + arow * 80 + ach * 32;
    const uint32_t b0off = smb + G2_B0 * 2 + krow * 144 + nc * 16;
    const uint32_t b1off = smb + G2_B1 * 2 + krow * 144 + nc * 16;
    const uint32_t SSB = G2_STGH * 2;

    #pragma unroll
    for (int s = 0; s < NSTG - 1; s++) {
        int kb = s * KC;
        cpa16(aoff + s * SSB,      aptr + kb,     aval);
        cpa16(aoff + s * SSB + 16, aptr + kb + 8, aval);
        cpa16(b0off + s * SSB, bptr + (size_t)kb * TD,      16u);
        cpa16(b1off + s * SSB, bptr + (size_t)kb * TD + 64, 16u);
        cpa_commit();
    }

    float acc[2][8][4];
    #pragma unroll
    for (int i = 0; i < 2; i++)
        #pragma unroll
        for (int j = 0; j < 8; j++)
            #pragma unroll
            for (int q = 0; q < 4; q++) acc[i][j][q] = 0.f;

    const int mrow0 = (warp & 3) * 32;
    const uint32_t sBbase = (warp >> 2) ? (G2_B1 * 2) : (G2_B0 * 2);  // warp n-half
    const int aR = mrow0 + ((lane >> 3) & 1) * 8 + (lane & 7);
    const int aC = (lane >> 4) * 8;
    const int bR = ((lane >> 3) & 1) * 8 + (lane & 7);
    const int bC = (lane >> 4) * 8;                                   // + pair*16 (within 64)

    const int NC = (TF / 2) / KC;   // 128
    #pragma unroll 1
    for (int i = 0; i < NC; i++) {
        cpa_wait2();
        __syncthreads();
        {
            int s = (i + NSTG - 1) & 3;
            int kb = (i + NSTG - 1) * KC;
            if (kb < TF / 2) {
                cpa16(aoff + s * SSB,      aptr + kb,     aval);
                cpa16(aoff + s * SSB + 16, aptr + kb + 8, aval);
                cpa16(b0off + s * SSB, bptr + (size_t)kb * TD,      16u);
                cpa16(b1off + s * SSB, bptr + (size_t)kb * TD + 64, 16u);
            }
            cpa_commit();
        }
        const uint32_t sbase = smb + (i & 3) * SSB;
        #pragma unroll
        for (int ks = 0; ks < 2; ks++) {
            uint32_t a[2][4];
            #pragma unroll
            for (int mi = 0; mi < 2; mi++)
                ldmx4(a[mi], sbase + (aR + mi * 16) * 80 + (aC + ks * 16) * 2);
            #pragma unroll
            for (int p = 0; p < 4; p++) {
                uint32_t bb[4];
                ldmx4t(bb, sbase + sBbase + (bR + ks * 16) * 144 + (bC + p * 16) * 2);
                #pragma unroll
                for (int sub = 0; sub < 2; sub++) {
                    const int ni = p * 2 + sub;
                    #pragma unroll
                    for (int mi = 0; mi < 2; mi++)
                        mma_f16(acc[mi][ni], a[mi], bb[sub * 2], bb[sub * 2 + 1]);
                }
            }
        }
    }

    // epilogue: scale by gate, scatter to assignment slot (fp16)
    #pragma unroll
    for (int mi = 0; mi < 2; mi++) {
        const int rl = (warp & 3) * 32 + mi * 16 + grp;
        const int r0 = row0 + rl, r1 = row0 + rl + 8;
        int a0i = 0, a1i = 0; float w0 = 0.f, w1 = 0.f;
        if (r0 < cnt) { a0i = g_rowmap[seg + r0]; w0 = g_rowgate[seg + r0]; }
        if (r1 < cnt) { a1i = g_rowmap[seg + r1]; w1 = g_rowgate[seg + r1]; }
        #pragma unroll
        for (int ni = 0; ni < 8; ni++) {
            const int col = n0 + (warp >> 2) * 64 + ni * 8 + t4 * 2;
            if (r0 < cnt)
                *(__half2*)&Yout[(size_t)a0i * TD + col] =
                    __floats2half2_rn(w0 * acc[mi][ni][0], w0 * acc[mi][ni][1]);
            if (r1 < cnt)
                *(__half2*)&Yout[(size_t)a1i * TD + col] =
                    __floats2half2_rn(w1 * acc[mi][ni][2], w1 * acc[mi][ni][3]);
        }
    }
}

// ---------------- combine: out[t] = sum over 2 slots x 2 k-slices (half2 in, fp32 out) ----------------
__global__ void combine_kernel(float2* __restrict__ out) {
    int i = blockIdx.x * blockDim.x + threadIdx.x;   // TT*TD/2 pairs
    if (i >= TT * TD / 2) return;
    int t = i >> 10;            // / (TD/2)
    int dp = i & (TD / 2 - 1);
    size_t i0 = (size_t)(2 * t) * (TD / 2) + dp;
    size_t i1 = (size_t)(2 * t + 1) * (TD / 2) + dp;
    float2 a = __half22float2(((const __half2*)g_Y0h)[i0]);
    float2 b = __half22float2(((const __half2*)g_Y1h)[i0]);
    float2 c = __half22float2(((const __half2*)g_Y0h)[i1]);
    float2 d = __half22float2(((const __half2*)g_Y1h)[i1]);
    float2 r;
    r.x = (a.x + b.x) + (c.x + d.x);
    r.y = (a.y + b.y) + (c.y + d.y);
    out[i] = r;
}

// ---------------- launch ----------------
extern "C" void kernel_launch(void* const* d_in, const int* in_sizes, int n_in,
                              void* d_out, int out_size) {
    const float* x  = (const float*)d_in[0];
    const float* Wr = (const float*)d_in[1];
    const float* Wg = (const float*)d_in[2];
    const float* Wu = (const float*)d_in[3];
    const float* Wd = (const float*)d_in[4];
    float* out = (float*)d_out;

    static int attr_done = 0;
    if (!attr_done) {
        cudaFuncSetAttribute(gemm1_kernel, cudaFuncAttributeMaxDynamicSharedMemorySize, G1_SMEM);
        cudaFuncSetAttribute(gemm2_kernel, cudaFuncAttributeMaxDynamicSharedMemorySize, G2_SMEM);
        attr_done = 1;
    }

    // fused router + serial cvt (x + first f-halves of Wg/Wu)
    prep_kernel<<<PREP_NRB + PREP_NCB, 256>>>(x, Wr, (const float4*)Wg, (const float4*)Wu);
    offsets_kernel<<<1, 256>>>();
    scatter_kernel<<<NA / 256, 256>>>();

    // pass A: GEMM f [0,4096) + fused cvt of Wg/Wu second halves
    gemm1_kernel<<<dim3(16, G1_NYP + G1_NYC, TE), 256, G1_SMEM>>>(
        0, 0, (const float4*)Wg, (const float4*)Wu, (const float4*)Wd);
    // pass B: GEMM f [4096,8192) + fused cvt of Wd
    gemm1_kernel<<<dim3(16, G1_NYP + G1_NYC, TE), 256, G1_SMEM>>>(
        TF / 2, 1, (const float4*)Wg, (const float4*)Wu, (const float4*)Wd);

    gemm2_kernel<<<dim3(16, (TD / 128) * 2, TE), 256, G2_SMEM>>>();

    combine_kernel<<<(TT * TD / 2) / 256, 256>>>((float2*)out);
}

// round 16
// speedup vs baseline: 1.5106x; 1.0204x over previous
#include <cuda_runtime.h>
#include <cuda_fp16.h>
#include <cstdint>

// Problem constants: B=2, S=1024, D=2048, F=8192, E=4, K=2
#define TT 2048
#define TD 2048
#define TF 8192
#define TE 4
#define NA 4096

#define KC 32           // K per stage (fp16)
#define NSTG 5          // 5-slot ring, 2 stages consumed per barrier

// GEMM1 smem (halfs/stage): A[128][40] + G[32][72] + U[32][72]
#define G1_STGH (128*40 + 32*72 + 32*72)    // 9728 halfs = 19456 B
#define G1_GB (128*40)                      // 5120
#define G1_UB (128*40 + 32*72)              // 7424
#define G1_SMEM (G1_STGH*NSTG*2 + 512)

// GEMM2 smem (halfs/stage): A[128][40] + B0[32][72] + B1[32][72]
#define G2_STGH G1_STGH
#define G2_B0 (128*40)
#define G2_B1 (128*40 + 32*72)
#define G2_SMEM (G2_STGH*NSTG*2)

#define NX4 (TT*TD/4)
#define NW4 (TE*TD*TF/4)        // float4 count per full weight tensor
#define NWH4 (NW4/2)            // float4 count per half (in f) of Wg or Wu

// gemm1 grid.y per pass: 64 GEMM panels + 4 cvt panels (16*4*4 = 256 cvt CTAs)
#define G1_NYP 64
#define G1_NYC 4

// prep kernel: 256 router blocks + 8192 cvt blocks
#define PREP_NRB 256
#define PREP_NCB 8192

// ---------------- device scratch ----------------
__device__ int    g_counts[TE];
__device__ int    g_fill[TE];
__device__ int    g_offs[TE + 1];
__device__ int    g_eidx[NA];
__device__ float  g_gate[NA];
__device__ int    g_rowmap[NA];
__device__ float  g_rowgate[NA];
__device__ __half g_Xh[(size_t)TT * TD];
__device__ __half g_Wgh[(size_t)TE * TD * TF];
__device__ __half g_Wuh[(size_t)TE * TD * TF];
__device__ __half g_Wdh[(size_t)TE * TF * TD];
__device__ __half g_Hh[(size_t)NA * TF];
__device__ __half g_Y0h[(size_t)NA * TD];   // split-K slice 0 (fp16)
__device__ __half g_Y1h[(size_t)NA * TD];   // split-K slice 1 (fp16)

// ---------------- helpers ----------------
__device__ __forceinline__ uint32_t smem_u32(const void* p) {
    uint32_t a;
    asm("{ .reg .u64 t; cvta.to.shared.u64 t, %1; cvt.u32.u64 %0, t; }" : "=r"(a) : "l"(p));
    return a;
}
__device__ __forceinline__ void cpa16(uint32_t dst, const void* src, uint32_t valid) {
    asm volatile("cp.async.cg.shared.global [%0], [%1], 16, %2;" :: "r"(dst), "l"(src), "r"(valid) : "memory");
}
__device__ __forceinline__ void cpa_commit() { asm volatile("cp.async.commit_group;" ::: "memory"); }
__device__ __forceinline__ void cpa_wait1()  { asm volatile("cp.async.wait_group 1;" ::: "memory"); }

__device__ __forceinline__ void ldmx4(uint32_t* r, uint32_t addr) {
    asm volatile("ldmatrix.sync.aligned.m8n8.x4.shared.b16 {%0,%1,%2,%3}, [%4];"
                 : "=r"(r[0]), "=r"(r[1]), "=r"(r[2]), "=r"(r[3]) : "r"(addr));
}
__device__ __forceinline__ void ldmx4t(uint32_t* r, uint32_t addr) {
    asm volatile("ldmatrix.sync.aligned.m8n8.x4.trans.shared.b16 {%0,%1,%2,%3}, [%4];"
                 : "=r"(r[0]), "=r"(r[1]), "=r"(r[2]), "=r"(r[3]) : "r"(addr));
}
__device__ __forceinline__ void mma_f16(float* c, const uint32_t* a, uint32_t b0, uint32_t b1) {
    asm volatile(
        "mma.sync.aligned.m16n8k16.row.col.f32.f16.f16.f32 "
        "{%0,%1,%2,%3}, {%4,%5,%6,%7}, {%8,%9}, {%0,%1,%2,%3};"
        : "+f"(c[0]), "+f"(c[1]), "+f"(c[2]), "+f"(c[3])
        : "r"(a[0]), "r"(a[1]), "r"(a[2]), "r"(a[3]), "r"(b0), "r"(b1));
}
__device__ __forceinline__ uint32_t packh2(float a, float b) {
    __half2 h = __floats2half2_rn(a, b);
    return *(uint32_t*)&h;
}

// ---------------- prep: fused router + fp32->fp16 cvt (x, Wg/Wu first f-halves) ----------------
__global__ void prep_kernel(const float* __restrict__ x, const float* __restrict__ Wr,
                            const float4* __restrict__ Wg, const float4* __restrict__ Wu) {
    if (blockIdx.x < PREP_NRB) {
        int gw   = (int)((blockIdx.x * blockDim.x + threadIdx.x) >> 5);
        int lane = threadIdx.x & 31;
        if (gw >= TT) return;
        const float* xr = x + (size_t)gw * TD;
        float a0 = 0.f, a1 = 0.f, a2 = 0.f, a3 = 0.f;
        for (int d = lane; d < TD; d += 32) {
            float xv = xr[d];
            float4 w = *(const float4*)(Wr + d * 4);
            a0 += xv * w.x; a1 += xv * w.y; a2 += xv * w.z; a3 += xv * w.w;
        }
        #pragma unroll
        for (int o = 16; o; o >>= 1) {
            a0 += __shfl_xor_sync(0xffffffffu, a0, o);
            a1 += __shfl_xor_sync(0xffffffffu, a1, o);
            a2 += __shfl_xor_sync(0xffffffffu, a2, o);
            a3 += __shfl_xor_sync(0xffffffffu, a3, o);
        }
        if (lane == 0) {
            float l[4] = {a0, a1, a2, a3};
            float m = fmaxf(fmaxf(l[0], l[1]), fmaxf(l[2], l[3]));
            float p[4]; float s = 0.f;
            #pragma unroll
            for (int i = 0; i < 4; i++) { p[i] = __expf(l[i] - m); s += p[i]; }
            float inv = 1.0f / s;
            int i0 = 0;
            #pragma unroll
            for (int i = 1; i < 4; i++) if (p[i] > p[i0]) i0 = i;
            int i1 = (i0 == 0) ? 1 : 0;
            #pragma unroll
            for (int i = 0; i < 4; i++) if (i != i0 && p[i] > p[i1]) i1 = i;
            g_eidx[gw * 2]     = i0; g_gate[gw * 2]     = p[i0] * inv;
            g_eidx[gw * 2 + 1] = i1; g_gate[gw * 2 + 1] = p[i1] * inv;
        }
        return;
    }

    const size_t total = (size_t)NX4 + 2 * (size_t)NWH4;
    const size_t stride = (size_t)PREP_NCB * 256;
    for (size_t i = (size_t)(blockIdx.x - PREP_NRB) * 256 + threadIdx.x; i < total; i += stride) {
        const float4* s;
        uint2* d;
        if (i < NX4) { s = (const float4*)x + i; d = (uint2*)g_Xh + i; }
        else if (i < NX4 + (size_t)NWH4) {
            size_t j = i - NX4;
            size_t row = j >> 10, col = j & 1023;
            size_t full = (row << 11) + col;
            s = Wg + full; d = (uint2*)g_Wgh + full;
        } else {
            size_t j = i - NX4 - (size_t)NWH4;
            size_t row = j >> 10, col = j & 1023;
            size_t full = (row << 11) + col;
            s = Wu + full; d = (uint2*)g_Wuh + full;
        }
        float4 v = *s;
        uint2 o;
        o.x = packh2(v.x, v.y);
        o.y = packh2(v.z, v.w);
        *d = o;
    }
}

// ---------------- offsets ----------------
__global__ void offsets_kernel() {
    __shared__ int cnt[TE];
    int tid = threadIdx.x;
    if (tid < TE) cnt[tid] = 0;
    __syncthreads();
    for (int i = tid; i < NA; i += 256) atomicAdd(&cnt[g_eidx[i]], 1);
    __syncthreads();
    if (tid == 0) {
        int s = 0;
        for (int e = 0; e < TE; e++) { g_counts[e] = cnt[e]; g_offs[e] = s; s += cnt[e]; }
        g_offs[TE] = s;
    }
    if (tid < TE) g_fill[tid] = 0;
}

__global__ void scatter_kernel() {
    int a = blockIdx.x * blockDim.x + threadIdx.x;
    if (a >= NA) return;
    int e = g_eidx[a];
    int pos = g_offs[e] + atomicAdd(&g_fill[e], 1);
    g_rowmap[pos]  = a;
    g_rowgate[pos] = g_gate[a];
}

// ---------------- GEMM1 (half-F pass) + fused conversion ----------------
__global__ __launch_bounds__(256, 2) void gemm1_kernel(
    int f_base, int cvt_mode,
    const float4* __restrict__ Wg, const float4* __restrict__ Wu, const float4* __restrict__ Wd) {
    // ---- fused conversion blocks ----
    if (blockIdx.y >= G1_NYP) {
        const int cid = blockIdx.x + 16 * ((blockIdx.y - G1_NYP) + G1_NYC * blockIdx.z);
        const size_t nthreads = (size_t)256 * G1_NYC * 16 * TE;  // 65536
        if (cvt_mode == 0) {
            for (size_t j = (size_t)cid * 256 + threadIdx.x; j < 2 * (size_t)NWH4; j += nthreads) {
                const float4* s; uint2* d;
                size_t jj = (j < (size_t)NWH4) ? j : j - (size_t)NWH4;
                size_t row = jj >> 10, col = jj & 1023;
                size_t full = (row << 11) + 1024 + col;
                if (j < (size_t)NWH4) { s = Wg + full; d = (uint2*)g_Wgh + full; }
                else                  { s = Wu + full; d = (uint2*)g_Wuh + full; }
                float4 v = *s;
                uint2 o;
                o.x = packh2(v.x, v.y);
                o.y = packh2(v.z, v.w);
                *d = o;
            }
        } else {
            for (size_t j = (size_t)cid * 256 + threadIdx.x; j < (size_t)NW4; j += nthreads) {
                float4 v = Wd[j];
                uint2 o;
                o.x = packh2(v.x, v.y);
                o.y = packh2(v.z, v.w);
                ((uint2*)g_Wdh)[j] = o;
            }
        }
        return;
    }

    const int e    = blockIdx.z;
    const int cnt  = g_counts[e];
    const int row0 = blockIdx.x * 128;
    if (row0 >= cnt) return;
    const int seg = g_offs[e];
    const int f0  = f_base + blockIdx.y * 64;

    extern __shared__ __half sm[];
    int* rid = (int*)(sm + G1_STGH * NSTG);

    const int tid = threadIdx.x, lane = tid & 31, warp = tid >> 5;
    const int grp = lane >> 2, t4 = lane & 3;

    if (tid < 128) {
        int r = row0 + tid;
        rid[tid] = (r < cnt) ? (g_rowmap[seg + r] >> 1) : -1;
    }
    __syncthreads();

    // loaders
    const int arow = tid >> 1, ach = (tid & 1);        // A: 2 x 16B
    const int tok  = rid[arow];
    const uint32_t aval = (tok >= 0) ? 16u : 0u;
    const __half* aptr = g_Xh + (size_t)(tok < 0 ? 0 : tok) * TD + ach * 16;
    const int krow = tid >> 3, nc = tid & 7;           // G/U: 1 x 16B each
    const __half* gptr = g_Wgh + ((size_t)e * TD + krow) * TF + f0 + nc * 8;
    const __half* uptr = g_Wuh + ((size_t)e * TD + krow) * TF + f0 + nc * 8;

    const uint32_t smb = smem_u32(sm);
    const uint32_t aoff = smb + arow * 80 + ach * 32;
    const uint32_t goff = smb + G1_GB * 2 + krow * 144 + nc * 16;
    const uint32_t uoff = smb + G1_UB * 2 + krow * 144 + nc * 16;
    const uint32_t SSB = G1_STGH * 2;

    // prologue: stages 0,1,2
    #pragma unroll
    for (int s = 0; s < 3; s++) {
        int kb = s * KC;
        cpa16(aoff + s * SSB,      aptr + kb,     aval);
        cpa16(aoff + s * SSB + 16, aptr + kb + 8, aval);
        cpa16(goff + s * SSB, gptr + (size_t)kb * TF, 16u);
        cpa16(uoff + s * SSB, uptr + (size_t)kb * TF, 16u);
        cpa_commit();
    }

    float accG[2][4][4], accU[2][4][4];
    #pragma unroll
    for (int i = 0; i < 2; i++)
        #pragma unroll
        for (int j = 0; j < 4; j++)
            #pragma unroll
            for (int q = 0; q < 4; q++) { accG[i][j][q] = 0.f; accU[i][j][q] = 0.f; }

    // ldmatrix lane maps
    const int mrow0 = (warp & 3) * 32;
    const int ncol0 = (warp >> 2) * 32;
    const int aR = mrow0 + ((lane >> 3) & 1) * 8 + (lane & 7);
    const int aC = (lane >> 4) * 8;
    const int bR = ((lane >> 3) & 1) * 8 + (lane & 7);
    const int bC = ncol0 + (lane >> 4) * 8;

    const int NP = (TD / KC) / 2;   // 32 pairs
    int s0 = 0;
    #pragma unroll 1
    for (int p = 0; p < NP; p++) {
        cpa_wait1();
        __syncthreads();
        // issue stages 2p+3, 2p+4
        #pragma unroll
        for (int q = 0; q < 2; q++) {
            int sj = s0 + 3 + q; if (sj >= NSTG) sj -= NSTG;
            int kb = (2 * p + 3 + q) * KC;
            if (kb < TD) {
                cpa16(aoff + sj * SSB,      aptr + kb,     aval);
                cpa16(aoff + sj * SSB + 16, aptr + kb + 8, aval);
                cpa16(goff + sj * SSB, gptr + (size_t)kb * TF, 16u);
                cpa16(uoff + sj * SSB, uptr + (size_t)kb * TF, 16u);
            }
            cpa_commit();
        }
        // compute stages 2p, 2p+1
        #pragma unroll
        for (int k2 = 0; k2 < 2; k2++) {
            int ss = s0 + k2; if (ss >= NSTG) ss -= NSTG;
            const uint32_t sbase = smb + ss * SSB;
            #pragma unroll
            for (int ks = 0; ks < 2; ks++) {
                uint32_t a[2][4];
                #pragma unroll
                for (int mi = 0; mi < 2; mi++)
                    ldmx4(a[mi], sbase + (aR + mi * 16) * 80 + (aC + ks * 16) * 2);
                uint32_t bg[2][4], bu[2][4];
                #pragma unroll
                for (int pp = 0; pp < 2; pp++) {
                    uint32_t ro = (bR + ks * 16) * 144 + (bC + pp * 16) * 2;
                    ldmx4t(bg[pp], sbase + G1_GB * 2 + ro);
                    ldmx4t(bu[pp], sbase + G1_UB * 2 + ro);
                }
                #pragma unroll
                for (int pp = 0; pp < 2; pp++)
                    #pragma unroll
                    for (int sub = 0; sub < 2; sub++) {
                        const int ni = pp * 2 + sub;
                        #pragma unroll
                        for (int mi = 0; mi < 2; mi++) {
                            mma_f16(accG[mi][ni], a[mi], bg[pp][sub * 2], bg[pp][sub * 2 + 1]);
                            mma_f16(accU[mi][ni], a[mi], bu[pp][sub * 2], bu[pp][sub * 2 + 1]);
                        }
                    }
            }
        }
        s0 += 2; if (s0 >= NSTG) s0 -= NSTG;
    }

    // epilogue: h = silu(g)*u -> g_Hh (fp16)
    #pragma unroll
    for (int mi = 0; mi < 2; mi++) {
        const int rl = (warp & 3) * 32 + mi * 16 + grp;
        const int r0 = row0 + rl, r1 = row0 + rl + 8;
        #pragma unroll
        for (int ni = 0; ni < 4; ni++) {
            const int col = f0 + (warp >> 2) * 32 + ni * 8 + t4 * 2;
            if (r0 < cnt) {
                float gg0 = accG[mi][ni][0], uu0 = accU[mi][ni][0];
                float gg1 = accG[mi][ni][1], uu1 = accU[mi][ni][1];
                float h0 = __fdividef(gg0 * uu0, 1.0f + __expf(-gg0));
                float h1 = __fdividef(gg1 * uu1, 1.0f + __expf(-gg1));
                *(__half2*)&g_Hh[(size_t)(seg + r0) * TF + col] = __floats2half2_rn(h0, h1);
            }
            if (r1 < cnt) {
                float gg0 = accG[mi][ni][2], uu0 = accU[mi][ni][2];
                float gg1 = accG[mi][ni][3], uu1 = accU[mi][ni][3];
                float h0 = __fdividef(gg0 * uu0, 1.0f + __expf(-gg0));
                float h1 = __fdividef(gg1 * uu1, 1.0f + __expf(-gg1));
                *(__half2*)&g_Hh[(size_t)(seg + r1) * TF + col] = __floats2half2_rn(h0, h1);
            }
        }
    }
}

// ---------------- GEMM2: Y = gate * (H * Wd)  [fp16, split-K x2, paired stages] ----------------
__global__ __launch_bounds__(256, 2) void gemm2_kernel() {
    const int e    = blockIdx.z;
    const int cnt  = g_counts[e];
    const int row0 = blockIdx.x * 128;
    if (row0 >= cnt) return;
    const int seg = g_offs[e];
    const int n0  = (blockIdx.y >> 1) * 128;
    const int ksl = blockIdx.y & 1;
    const int k0  = ksl * (TF / 2);
    __half* Yout = ksl ? g_Y1h : g_Y0h;

    extern __shared__ __half sm[];
    const int tid = threadIdx.x, lane = tid & 31, warp = tid >> 5;
    const int grp = lane >> 2, t4 = lane & 3;

    const int arow = tid >> 1, ach = (tid & 1);
    const uint32_t aval = (row0 + arow < cnt) ? 16u : 0u;
    const __half* aptr = g_Hh + (size_t)(seg + ((row0 + arow < cnt) ? row0 + arow : 0)) * TF + k0 + ach * 16;
    const int krow = tid >> 3, nc = tid & 7;
    const __half* bptr = g_Wdh + ((size_t)e * TF + k0 + krow) * TD + n0 + nc * 8;

    const uint32_t smb = smem_u32(sm);
    const uint32_t aoff = smb + arow * 80 + ach * 32;
    const uint32_t b0off = smb + G2_B0 * 2 + krow * 144 + nc * 16;
    const uint32_t b1off = smb + G2_B1 * 2 + krow * 144 + nc * 16;
    const uint32_t SSB = G2_STGH * 2;

    #pragma unroll
    for (int s = 0; s < 3; s++) {
        int kb = s * KC;
        cpa16(aoff + s * SSB,      aptr + kb,     aval);
        cpa16(aoff + s * SSB + 16, aptr + kb + 8, aval);
        cpa16(b0off + s * SSB, bptr + (size_t)kb * TD,      16u);
        cpa16(b1off + s * SSB, bptr + (size_t)kb * TD + 64, 16u);
        cpa_commit();
    }

    float acc[2][8][4];
    #pragma unroll
    for (int i = 0; i < 2; i++)
        #pragma unroll
        for (int j = 0; j < 8; j++)
            #pragma unroll
            for (int q = 0; q < 4; q++) acc[i][j][q] = 0.f;

    const int mrow0 = (warp & 3) * 32;
    const uint32_t sBbase = (warp >> 2) ? (G2_B1 * 2) : (G2_B0 * 2);
    const int aR = mrow0 + ((lane >> 3) & 1) * 8 + (lane & 7);
    const int aC = (lane >> 4) * 8;
    const int bR = ((lane >> 3) & 1) * 8 + (lane & 7);
    const int bC = (lane >> 4) * 8;

    const int NP = ((TF / 2) / KC) / 2;   // 64 pairs
    int s0 = 0;
    #pragma unroll 1
    for (int p = 0; p < NP; p++) {
        cpa_wait1();
        __syncthreads();
        #pragma unroll
        for (int q = 0; q < 2; q++) {
            int sj = s0 + 3 + q; if (sj >= NSTG) sj -= NSTG;
            int kb = (2 * p + 3 + q) * KC;
            if (kb < TF / 2) {
                cpa16(aoff + sj * SSB,      aptr + kb,     aval);
                cpa16(aoff + sj * SSB + 16, aptr + kb + 8, aval);
                cpa16(b0off + sj * SSB, bptr + (size_t)kb * TD,      16u);
                cpa16(b1off + sj * SSB, bptr + (size_t)kb * TD + 64, 16u);
            }
            cpa_commit();
        }
        #pragma unroll
        for (int k2 = 0; k2 < 2; k2++) {
            int ss = s0 + k2; if (ss >= NSTG) ss -= NSTG;
            const uint32_t sbase = smb + ss * SSB;
            #pragma unroll
            for (int ks = 0; ks < 2; ks++) {
                uint32_t a[2][4];
                #pragma unroll
                for (int mi = 0; mi < 2; mi++)
                    ldmx4(a[mi], sbase + (aR + mi * 16) * 80 + (aC + ks * 16) * 2);
                #pragma unroll
                for (int pp = 0; pp < 4; pp++) {
                    uint32_t bb[4];
                    ldmx4t(bb, sbase + sBbase + (bR + ks * 16) * 144 + (bC + pp * 16) * 2);
                    #pragma unroll
                    for (int sub = 0; sub < 2; sub++) {
                        const int ni = pp * 2 + sub;
                        #pragma unroll
                        for (int mi = 0; mi < 2; mi++)
                            mma_f16(acc[mi][ni], a[mi], bb[sub * 2], bb[sub * 2 + 1]);
                    }
                }
            }
        }
        s0 += 2; if (s0 >= NSTG) s0 -= NSTG;
    }

    // epilogue: scale by gate, scatter to assignment slot (fp16)
    #pragma unroll
    for (int mi = 0; mi < 2; mi++) {
        const int rl = (warp & 3) * 32 + mi * 16 + grp;
        const int r0 = row0 + rl, r1 = row0 + rl + 8;
        int a0i = 0, a1i = 0; float w0 = 0.f, w1 = 0.f;
        if (r0 < cnt) { a0i = g_rowmap[seg + r0]; w0 = g_rowgate[seg + r0]; }
        if (r1 < cnt) { a1i = g_rowmap[seg + r1]; w1 = g_rowgate[seg + r1]; }
        #pragma unroll
        for (int ni = 0; ni < 8; ni++) {
            const int col = n0 + (warp >> 2) * 64 + ni * 8 + t4 * 2;
            if (r0 < cnt)
                *(__half2*)&Yout[(size_t)a0i * TD + col] =
                    __floats2half2_rn(w0 * acc[mi][ni][0], w0 * acc[mi][ni][1]);
            if (r1 < cnt)
                *(__half2*)&Yout[(size_t)a1i * TD + col] =
                    __floats2half2_rn(w1 * acc[mi][ni][2], w1 * acc[mi][ni][3]);
        }
    }
}

// ---------------- combine ----------------
__global__ void combine_kernel(float2* __restrict__ out) {
    int i = blockIdx.x * blockDim.x + threadIdx.x;
    if (i >= TT * TD / 2) return;
    int t = i >> 10;
    int dp = i & (TD / 2 - 1);
    size_t i0 = (size_t)(2 * t) * (TD / 2) + dp;
    size_t i1 = (size_t)(2 * t + 1) * (TD / 2) + dp;
    float2 a = __half22float2(((const __half2*)g_Y0h)[i0]);
    float2 b = __half22float2(((const __half2*)g_Y1h)[i0]);
    float2 c = __half22float2(((const __half2*)g_Y0h)[i1]);
    float2 d = __half22float2(((const __half2*)g_Y1h)[i1]);
    float2 r;
    r.x = (a.x + b.x) + (c.x + d.x);
    r.y = (a.y + b.y) + (c.y + d.y);
    out[i] = r;
}

// ---------------- launch ----------------
extern "C" void kernel_launch(void* const* d_in, const int* in_sizes, int n_in,
                              void* d_out, int out_size) {
    const float* x  = (const float*)d_in[0];
    const float* Wr = (const float*)d_in[1];
    const float* Wg = (const float*)d_in[2];
    const float* Wu = (const float*)d_in[3];
    const float* Wd = (const float*)d_in[4];
    float* out = (float*)d_out;

    static int attr_done = 0;
    if (!attr_done) {
        cudaFuncSetAttribute(gemm1_kernel, cudaFuncAttributeMaxDynamicSharedMemorySize, G1_SMEM);
        cudaFuncSetAttribute(gemm2_kernel, cudaFuncAttributeMaxDynamicSharedMemorySize, G2_SMEM);
        attr_done = 1;
    }

    prep_kernel<<<PREP_NRB + PREP_NCB, 256>>>(x, Wr, (const float4*)Wg, (const float4*)Wu);
    offsets_kernel<<<1, 256>>>();
    scatter_kernel<<<NA / 256, 256>>>();

    gemm1_kernel<<<dim3(16, G1_NYP + G1_NYC, TE), 256, G1_SMEM>>>(
        0, 0, (const float4*)Wg, (const float4*)Wu, (const float4*)Wd);
    gemm1_kernel<<<dim3(16, G1_NYP + G1_NYC, TE), 256, G1_SMEM>>>(
        TF / 2, 1, (const float4*)Wg, (const float4*)Wu, (const float4*)Wd);

    gemm2_kernel<<<dim3(16, (TD / 128) * 2, TE), 256, G2_SMEM>>>();

    combine_kernel<<<(TT * TD / 2) / 256, 256>>>((float2*)out);
}

// round 17
// speedup vs baseline: 1.5238x; 1.0087x over previous
#include <cuda_runtime.h>
#include <cuda_fp16.h>
#include <cstdint>

// Problem constants: B=2, S=1024, D=2048, F=8192, E=4, K=2
#define TT 2048
#define TD 2048
#define TF 8192
#define TE 4
#define NA 4096

#define KC 32           // K per stage (fp16)
#define NSTG 5          // 5-slot ring, 2 stages consumed per barrier

// GEMM1 smem (halfs/stage): A[128][40] + G[32][72] + U[32][72]
#define G1_STGH (128*40 + 32*72 + 32*72)    // 9728 halfs = 19456 B
#define G1_GB (128*40)                      // 5120
#define G1_UB (128*40 + 32*72)              // 7424
#define G1_SMEM (G1_STGH*NSTG*2 + 512)

// GEMM2 smem (halfs/stage): A[128][40] + B0[32][72] + B1[32][72]
#define G2_STGH G1_STGH
#define G2_B0 (128*40)
#define G2_B1 (128*40 + 32*72)
#define G2_SMEM (G2_STGH*NSTG*2)

#define NX4 (TT*TD/4)
#define NW4 (TE*TD*TF/4)        // float4 count per full weight tensor
#define NWH4 (NW4/2)            // float4 count per half (in f) of Wg or Wu

// gemm1 grid.y per pass: 64 GEMM panels + 4 cvt panels (16*4*4 = 256 cvt CTAs)
#define G1_NYP 64
#define G1_NYC 4

// prep kernel: 256 router blocks + 8192 cvt blocks
#define PREP_NRB 256
#define PREP_NCB 8192

// ---------------- device scratch ----------------
__device__ int    g_counts[TE];
__device__ int    g_fill[TE];
__device__ int    g_offs[TE + 1];
__device__ int    g_eidx[NA];
__device__ float  g_gate[NA];
__device__ int    g_rowmap[NA];
__device__ float  g_rowgate[NA];
__device__ __half g_Xh[(size_t)TT * TD];
__device__ __half g_Wgh[(size_t)TE * TD * TF];
__device__ __half g_Wuh[(size_t)TE * TD * TF];
__device__ __half g_Wdh[(size_t)TE * TF * TD];
__device__ __half g_Hh[(size_t)NA * TF];
__device__ __half g_Y0h[(size_t)NA * TD];   // split-K slice 0 (fp16)
__device__ __half g_Y1h[(size_t)NA * TD];   // split-K slice 1 (fp16)

// ---------------- helpers ----------------
__device__ __forceinline__ uint32_t smem_u32(const void* p) {
    uint32_t a;
    asm("{ .reg .u64 t; cvta.to.shared.u64 t, %1; cvt.u32.u64 %0, t; }" : "=r"(a) : "l"(p));
    return a;
}
__device__ __forceinline__ void cpa16(uint32_t dst, const void* src, uint32_t valid) {
    asm volatile("cp.async.cg.shared.global [%0], [%1], 16, %2;" :: "r"(dst), "l"(src), "r"(valid) : "memory");
}
__device__ __forceinline__ void cpa_commit() { asm volatile("cp.async.commit_group;" ::: "memory"); }
__device__ __forceinline__ void cpa_wait1()  { asm volatile("cp.async.wait_group 1;" ::: "memory"); }

__device__ __forceinline__ void ldmx4(uint32_t* r, uint32_t addr) {
    asm volatile("ldmatrix.sync.aligned.m8n8.x4.shared.b16 {%0,%1,%2,%3}, [%4];"
                 : "=r"(r[0]), "=r"(r[1]), "=r"(r[2]), "=r"(r[3]) : "r"(addr));
}
__device__ __forceinline__ void ldmx4t(uint32_t* r, uint32_t addr) {
    asm volatile("ldmatrix.sync.aligned.m8n8.x4.trans.shared.b16 {%0,%1,%2,%3}, [%4];"
                 : "=r"(r[0]), "=r"(r[1]), "=r"(r[2]), "=r"(r[3]) : "r"(addr));
}
__device__ __forceinline__ void mma_f16(float* c, const uint32_t* a, uint32_t b0, uint32_t b1) {
    asm volatile(
        "mma.sync.aligned.m16n8k16.row.col.f32.f16.f16.f32 "
        "{%0,%1,%2,%3}, {%4,%5,%6,%7}, {%8,%9}, {%0,%1,%2,%3};"
        : "+f"(c[0]), "+f"(c[1]), "+f"(c[2]), "+f"(c[3])
        : "r"(a[0]), "r"(a[1]), "r"(a[2]), "r"(a[3]), "r"(b0), "r"(b1));
}
__device__ __forceinline__ uint32_t packh2(float a, float b) {
    __half2 h = __floats2half2_rn(a, b);
    return *(uint32_t*)&h;
}

// ---------------- prep: fused router + fp32->fp16 cvt (x, Wg/Wu first f-halves) ----------------
__global__ void prep_kernel(const float* __restrict__ x, const float* __restrict__ Wr,
                            const float4* __restrict__ Wg, const float4* __restrict__ Wu) {
    if (blockIdx.x < PREP_NRB) {
        int gw   = (int)((blockIdx.x * blockDim.x + threadIdx.x) >> 5);
        int lane = threadIdx.x & 31;
        if (gw >= TT) return;
        const float* xr = x + (size_t)gw * TD;
        float a0 = 0.f, a1 = 0.f, a2 = 0.f, a3 = 0.f;
        for (int d = lane; d < TD; d += 32) {
            float xv = xr[d];
            float4 w = *(const float4*)(Wr + d * 4);
            a0 += xv * w.x; a1 += xv * w.y; a2 += xv * w.z; a3 += xv * w.w;
        }
        #pragma unroll
        for (int o = 16; o; o >>= 1) {
            a0 += __shfl_xor_sync(0xffffffffu, a0, o);
            a1 += __shfl_xor_sync(0xffffffffu, a1, o);
            a2 += __shfl_xor_sync(0xffffffffu, a2, o);
            a3 += __shfl_xor_sync(0xffffffffu, a3, o);
        }
        if (lane == 0) {
            float l[4] = {a0, a1, a2, a3};
            float m = fmaxf(fmaxf(l[0], l[1]), fmaxf(l[2], l[3]));
            float p[4]; float s = 0.f;
            #pragma unroll
            for (int i = 0; i < 4; i++) { p[i] = __expf(l[i] - m); s += p[i]; }
            float inv = 1.0f / s;
            int i0 = 0;
            #pragma unroll
            for (int i = 1; i < 4; i++) if (p[i] > p[i0]) i0 = i;
            int i1 = (i0 == 0) ? 1 : 0;
            #pragma unroll
            for (int i = 0; i < 4; i++) if (i != i0 && p[i] > p[i1]) i1 = i;
            g_eidx[gw * 2]     = i0; g_gate[gw * 2]     = p[i0] * inv;
            g_eidx[gw * 2 + 1] = i1; g_gate[gw * 2 + 1] = p[i1] * inv;
        }
        return;
    }

    const size_t total = (size_t)NX4 + 2 * (size_t)NWH4;
    const size_t stride = (size_t)PREP_NCB * 256;
    for (size_t i = (size_t)(blockIdx.x - PREP_NRB) * 256 + threadIdx.x; i < total; i += stride) {
        const float4* s;
        uint2* d;
        if (i < NX4) { s = (const float4*)x + i; d = (uint2*)g_Xh + i; }
        else if (i < NX4 + (size_t)NWH4) {
            size_t j = i - NX4;
            size_t row = j >> 10, col = j & 1023;
            size_t full = (row << 11) + col;
            s = Wg + full; d = (uint2*)g_Wgh + full;
        } else {
            size_t j = i - NX4 - (size_t)NWH4;
            size_t row = j >> 10, col = j & 1023;
            size_t full = (row << 11) + col;
            s = Wu + full; d = (uint2*)g_Wuh + full;
        }
        float4 v = *s;
        uint2 o;
        o.x = packh2(v.x, v.y);
        o.y = packh2(v.z, v.w);
        *d = o;
    }
}

// ---------------- offsets ----------------
__global__ void offsets_kernel() {
    __shared__ int cnt[TE];
    int tid = threadIdx.x;
    if (tid < TE) cnt[tid] = 0;
    __syncthreads();
    for (int i = tid; i < NA; i += 256) atomicAdd(&cnt[g_eidx[i]], 1);
    __syncthreads();
    if (tid == 0) {
        int s = 0;
        for (int e = 0; e < TE; e++) { g_counts[e] = cnt[e]; g_offs[e] = s; s += cnt[e]; }
        g_offs[TE] = s;
    }
    if (tid < TE) g_fill[tid] = 0;
}

__global__ void scatter_kernel() {
    int a = blockIdx.x * blockDim.x + threadIdx.x;
    if (a >= NA) return;
    int e = g_eidx[a];
    int pos = g_offs[e] + atomicAdd(&g_fill[e], 1);
    g_rowmap[pos]  = a;
    g_rowgate[pos] = g_gate[a];
}

// ---------------- GEMM1 (half-F pass) + fused conversion ----------------
__global__ __launch_bounds__(256, 2) void gemm1_kernel(
    int f_base, int cvt_mode,
    const float4* __restrict__ Wg, const float4* __restrict__ Wu, const float4* __restrict__ Wd) {
    // ---- fused conversion blocks ----
    if (blockIdx.y >= G1_NYP) {
        const int cid = blockIdx.x + 16 * ((blockIdx.y - G1_NYP) + G1_NYC * blockIdx.z);
        const size_t nthreads = (size_t)256 * G1_NYC * 16 * TE;  // 65536
        if (cvt_mode == 0) {
            for (size_t j = (size_t)cid * 256 + threadIdx.x; j < 2 * (size_t)NWH4; j += nthreads) {
                const float4* s; uint2* d;
                size_t jj = (j < (size_t)NWH4) ? j : j - (size_t)NWH4;
                size_t row = jj >> 10, col = jj & 1023;
                size_t full = (row << 11) + 1024 + col;
                if (j < (size_t)NWH4) { s = Wg + full; d = (uint2*)g_Wgh + full; }
                else                  { s = Wu + full; d = (uint2*)g_Wuh + full; }
                float4 v = *s;
                uint2 o;
                o.x = packh2(v.x, v.y);
                o.y = packh2(v.z, v.w);
                *d = o;
            }
        } else {
            for (size_t j = (size_t)cid * 256 + threadIdx.x; j < (size_t)NW4; j += nthreads) {
                float4 v = Wd[j];
                uint2 o;
                o.x = packh2(v.x, v.y);
                o.y = packh2(v.z, v.w);
                ((uint2*)g_Wdh)[j] = o;
            }
        }
        return;
    }

    const int e    = blockIdx.z;
    const int cnt  = g_counts[e];
    const int row0 = blockIdx.x * 128;
    if (row0 >= cnt) return;
    const int seg = g_offs[e];
    const int f0  = f_base + blockIdx.y * 64;

    extern __shared__ __half sm[];
    int* rid = (int*)(sm + G1_STGH * NSTG);

    const int tid = threadIdx.x, lane = tid & 31, warp = tid >> 5;
    const int grp = lane >> 2, t4 = lane & 3;

    if (tid < 128) {
        int r = row0 + tid;
        rid[tid] = (r < cnt) ? (g_rowmap[seg + r] >> 1) : -1;
    }
    __syncthreads();

    // loaders
    const int arow = tid >> 1, ach = (tid & 1);        // A: 2 x 16B
    const int tok  = rid[arow];
    const uint32_t aval = (tok >= 0) ? 16u : 0u;
    const __half* aptr = g_Xh + (size_t)(tok < 0 ? 0 : tok) * TD + ach * 16;
    const int krow = tid >> 3, nc = tid & 7;           // G/U: 1 x 16B each
    const __half* gptr = g_Wgh + ((size_t)e * TD + krow) * TF + f0 + nc * 8;
    const __half* uptr = g_Wuh + ((size_t)e * TD + krow) * TF + f0 + nc * 8;

    const uint32_t smb = smem_u32(sm);
    const uint32_t aoff = smb + arow * 80 + ach * 32;
    const uint32_t goff = smb + G1_GB * 2 + krow * 144 + nc * 16;
    const uint32_t uoff = smb + G1_UB * 2 + krow * 144 + nc * 16;
    const uint32_t SSB = G1_STGH * 2;

    // prologue: stages 0,1,2
    #pragma unroll
    for (int s = 0; s < 3; s++) {
        int kb = s * KC;
        cpa16(aoff + s * SSB,      aptr + kb,     aval);
        cpa16(aoff + s * SSB + 16, aptr + kb + 8, aval);
        cpa16(goff + s * SSB, gptr + (size_t)kb * TF, 16u);
        cpa16(uoff + s * SSB, uptr + (size_t)kb * TF, 16u);
        cpa_commit();
    }

    float accG[2][4][4], accU[2][4][4];
    #pragma unroll
    for (int i = 0; i < 2; i++)
        #pragma unroll
        for (int j = 0; j < 4; j++)
            #pragma unroll
            for (int q = 0; q < 4; q++) { accG[i][j][q] = 0.f; accU[i][j][q] = 0.f; }

    // ldmatrix lane maps
    const int mrow0 = (warp & 3) * 32;
    const int ncol0 = (warp >> 2) * 32;
    const int aR = mrow0 + ((lane >> 3) & 1) * 8 + (lane & 7);
    const int aC = (lane >> 4) * 8;
    const int bR = ((lane >> 3) & 1) * 8 + (lane & 7);
    const int bC = ncol0 + (lane >> 4) * 8;

    const int NP = (TD / KC) / 2;   // 32 pairs
    int s0 = 0;
    #pragma unroll 1
    for (int p = 0; p < NP; p++) {
        cpa_wait1();
        __syncthreads();
        // issue stages 2p+3, 2p+4
        #pragma unroll
        for (int q = 0; q < 2; q++) {
            int sj = s0 + 3 + q; if (sj >= NSTG) sj -= NSTG;
            int kb = (2 * p + 3 + q) * KC;
            if (kb < TD) {
                cpa16(aoff + sj * SSB,      aptr + kb,     aval);
                cpa16(aoff + sj * SSB + 16, aptr + kb + 8, aval);
                cpa16(goff + sj * SSB, gptr + (size_t)kb * TF, 16u);
                cpa16(uoff + sj * SSB, uptr + (size_t)kb * TF, 16u);
            }
            cpa_commit();
        }
        // compute 4 ks-blocks (2 stages x 2 k-halves), warp-rotated order
        // to stagger LDSM/MMA phases across warps on each SMSP.
        #pragma unroll
        for (int jj = 0; jj < 4; jj++) {
            const int j  = (jj + warp) & 3;
            const int k2 = j >> 1;
            const int ks = j & 1;
            int ss = s0 + k2; if (ss >= NSTG) ss -= NSTG;
            const uint32_t sbase = smb + ss * SSB;
            uint32_t a[2][4];
            #pragma unroll
            for (int mi = 0; mi < 2; mi++)
                ldmx4(a[mi], sbase + (aR + mi * 16) * 80 + (aC + ks * 16) * 2);
            uint32_t bg[2][4], bu[2][4];
            #pragma unroll
            for (int pp = 0; pp < 2; pp++) {
                uint32_t ro = (bR + ks * 16) * 144 + (bC + pp * 16) * 2;
                ldmx4t(bg[pp], sbase + G1_GB * 2 + ro);
                ldmx4t(bu[pp], sbase + G1_UB * 2 + ro);
            }
            #pragma unroll
            for (int pp = 0; pp < 2; pp++)
                #pragma unroll
                for (int sub = 0; sub < 2; sub++) {
                    const int ni = pp * 2 + sub;
                    #pragma unroll
                    for (int mi = 0; mi < 2; mi++) {
                        mma_f16(accG[mi][ni], a[mi], bg[pp][sub * 2], bg[pp][sub * 2 + 1]);
                        mma_f16(accU[mi][ni], a[mi], bu[pp][sub * 2], bu[pp][sub * 2 + 1]);
                    }
                }
        }
        s0 += 2; if (s0 >= NSTG) s0 -= NSTG;
    }

    // epilogue: h = silu(g)*u -> g_Hh (fp16)
    #pragma unroll
    for (int mi = 0; mi < 2; mi++) {
        const int rl = (warp & 3) * 32 + mi * 16 + grp;
        const int r0 = row0 + rl, r1 = row0 + rl + 8;
        #pragma unroll
        for (int ni = 0; ni < 4; ni++) {
            const int col = f0 + (warp >> 2) * 32 + ni * 8 + t4 * 2;
            if (r0 < cnt) {
                float gg0 = accG[mi][ni][0], uu0 = accU[mi][ni][0];
                float gg1 = accG[mi][ni][1], uu1 = accU[mi][ni][1];
                float h0 = __fdividef(gg0 * uu0, 1.0f + __expf(-gg0));
                float h1 = __fdividef(gg1 * uu1, 1.0f + __expf(-gg1));
                *(__half2*)&g_Hh[(size_t)(seg + r0) * TF + col] = __floats2half2_rn(h0, h1);
            }
            if (r1 < cnt) {
                float gg0 = accG[mi][ni][2], uu0 = accU[mi][ni][2];
                float gg1 = accG[mi][ni][3], uu1 = accU[mi][ni][3];
                float h0 = __fdividef(gg0 * uu0, 1.0f + __expf(-gg0));
                float h1 = __fdividef(gg1 * uu1, 1.0f + __expf(-gg1));
                *(__half2*)&g_Hh[(size_t)(seg + r1) * TF + col] = __floats2half2_rn(h0, h1);
            }
        }
    }
}

// ---------------- GEMM2: Y = gate * (H * Wd)  [fp16, split-K x2, staggered] ----------------
__global__ __launch_bounds__(256, 2) void gemm2_kernel() {
    const int e    = blockIdx.z;
    const int cnt  = g_counts[e];
    const int row0 = blockIdx.x * 128;
    if (row0 >= cnt) return;
    const int seg = g_offs[e];
    const int n0  = (blockIdx.y >> 1) * 128;
    const int ksl = blockIdx.y & 1;
    const int k0  = ksl * (TF / 2);
    __half* Yout = ksl ? g_Y1h : g_Y0h;

    extern __shared__ __half sm[];
    const int tid = threadIdx.x, lane = tid & 31, warp = tid >> 5;
    const int grp = lane >> 2, t4 = lane & 3;

    const int arow = tid >> 1, ach = (tid & 1);
    const uint32_t aval = (row0 + arow < cnt) ? 16u : 0u;
    const __half* aptr = g_Hh + (size_t)(seg + ((row0 + arow < cnt) ? row0 + arow : 0)) * TF + k0 + ach * 16;
    const int krow = tid >> 3, nc = tid & 7;
    const __half* bptr = g_Wdh + ((size_t)e * TF + k0 + krow) * TD + n0 + nc * 8;

    const uint32_t smb = smem_u32(sm);
    const uint32_t aoff = smb + arow * 80 + ach * 32;
    const uint32_t b0off = smb + G2_B0 * 2 + krow * 144 + nc * 16;
    const uint32_t b1off = smb + G2_B1 * 2 + krow * 144 + nc * 16;
    const uint32_t SSB = G2_STGH * 2;

    #pragma unroll
    for (int s = 0; s < 3; s++) {
        int kb = s * KC;
        cpa16(aoff + s * SSB,      aptr + kb,     aval);
        cpa16(aoff + s * SSB + 16, aptr + kb + 8, aval);
        cpa16(b0off + s * SSB, bptr + (size_t)kb * TD,      16u);
        cpa16(b1off + s * SSB, bptr + (size_t)kb * TD + 64, 16u);
        cpa_commit();
    }

    float acc[2][8][4];
    #pragma unroll
    for (int i = 0; i < 2; i++)
        #pragma unroll
        for (int j = 0; j < 8; j++)
            #pragma unroll
            for (int q = 0; q < 4; q++) acc[i][j][q] = 0.f;

    const int mrow0 = (warp & 3) * 32;
    const uint32_t sBbase = (warp >> 2) ? (G2_B1 * 2) : (G2_B0 * 2);
    const int aR = mrow0 + ((lane >> 3) & 1) * 8 + (lane & 7);
    const int aC = (lane >> 4) * 8;
    const int bR = ((lane >> 3) & 1) * 8 + (lane & 7);
    const int bC = (lane >> 4) * 8;

    const int NP = ((TF / 2) / KC) / 2;   // 64 pairs
    int s0 = 0;
    #pragma unroll 1
    for (int p = 0; p < NP; p++) {
        cpa_wait1();
        __syncthreads();
        #pragma unroll
        for (int q = 0; q < 2; q++) {
            int sj = s0 + 3 + q; if (sj >= NSTG) sj -= NSTG;
            int kb = (2 * p + 3 + q) * KC;
            if (kb < TF / 2) {
                cpa16(aoff + sj * SSB,      aptr + kb,     aval);
                cpa16(aoff + sj * SSB + 16, aptr + kb + 8, aval);
                cpa16(b0off + sj * SSB, bptr + (size_t)kb * TD,      16u);
                cpa16(b1off + sj * SSB, bptr + (size_t)kb * TD + 64, 16u);
            }
            cpa_commit();
        }
        // 4 ks-blocks, warp-rotated order
        #pragma unroll
        for (int jj = 0; jj < 4; jj++) {
            const int j  = (jj + warp) & 3;
            const int k2 = j >> 1;
            const int ks = j & 1;
            int ss = s0 + k2; if (ss >= NSTG) ss -= NSTG;
            const uint32_t sbase = smb + ss * SSB;
            uint32_t a[2][4];
            #pragma unroll
            for (int mi = 0; mi < 2; mi++)
                ldmx4(a[mi], sbase + (aR + mi * 16) * 80 + (aC + ks * 16) * 2);
            #pragma unroll
            for (int pp = 0; pp < 4; pp++) {
                uint32_t bb[4];
                ldmx4t(bb, sbase + sBbase + (bR + ks * 16) * 144 + (bC + pp * 16) * 2);
                #pragma unroll
                for (int sub = 0; sub < 2; sub++) {
                    const int ni = pp * 2 + sub;
                    #pragma unroll
                    for (int mi = 0; mi < 2; mi++)
                        mma_f16(acc[mi][ni], a[mi], bb[sub * 2], bb[sub * 2 + 1]);
                }
            }
        }
        s0 += 2; if (s0 >= NSTG) s0 -= NSTG;
    }

    // epilogue: scale by gate, scatter to assignment slot (fp16)
    #pragma unroll
    for (int mi = 0; mi < 2; mi++) {
        const int rl = (warp & 3) * 32 + mi * 16 + grp;
        const int r0 = row0 + rl, r1 = row0 + rl + 8;
        int a0i = 0, a1i = 0; float w0 = 0.f, w1 = 0.f;
        if (r0 < cnt) { a0i = g_rowmap[seg + r0]; w0 = g_rowgate[seg + r0]; }
        if (r1 < cnt) { a1i = g_rowmap[seg + r1]; w1 = g_rowgate[seg + r1]; }
        #pragma unroll
        for (int ni = 0; ni < 8; ni++) {
            const int col = n0 + (warp >> 2) * 64 + ni * 8 + t4 * 2;
            if (r0 < cnt)
                *(__half2*)&Yout[(size_t)a0i * TD + col] =
                    __floats2half2_rn(w0 * acc[mi][ni][0], w0 * acc[mi][ni][1]);
            if (r1 < cnt)
                *(__half2*)&Yout[(size_t)a1i * TD + col] =
                    __floats2half2_rn(w1 * acc[mi][ni][2], w1 * acc[mi][ni][3]);
        }
    }
}

// ---------------- combine ----------------
__global__ void combine_kernel(float2* __restrict__ out) {
    int i = blockIdx.x * blockDim.x + threadIdx.x;
    if (i >= TT * TD / 2) return;
    int t = i >> 10;
    int dp = i & (TD / 2 - 1);
    size_t i0 = (size_t)(2 * t) * (TD / 2) + dp;
    size_t i1 = (size_t)(2 * t + 1) * (TD / 2) + dp;
    float2 a = __half22float2(((const __half2*)g_Y0h)[i0]);
    float2 b = __half22float2(((const __half2*)g_Y1h)[i0]);
    float2 c = __half22float2(((const __half2*)g_Y0h)[i1]);
    float2 d = __half22float2(((const __half2*)g_Y1h)[i1]);
    float2 r;
    r.x = (a.x + b.x) + (c.x + d.x);
    r.y = (a.y + b.y) + (c.y + d.y);
    out[i] = r;
}

// ---------------- launch ----------------
extern "C" void kernel_launch(void* const* d_in, const int* in_sizes, int n_in,
                              void* d_out, int out_size) {
    const float* x  = (const float*)d_in[0];
    const float* Wr = (const float*)d_in[1];
    const float* Wg = (const float*)d_in[2];
    const float* Wu = (const float*)d_in[3];
    const float* Wd = (const float*)d_in[4];
    float* out = (float*)d_out;

    static int attr_done = 0;
    if (!attr_done) {
        cudaFuncSetAttribute(gemm1_kernel, cudaFuncAttributeMaxDynamicSharedMemorySize, G1_SMEM);
        cudaFuncSetAttribute(gemm2_kernel, cudaFuncAttributeMaxDynamicSharedMemorySize, G2_SMEM);
        attr_done = 1;
    }

    prep_kernel<<<PREP_NRB + PREP_NCB, 256>>>(x, Wr, (const float4*)Wg, (const float4*)Wu);
    offsets_kernel<<<1, 256>>>();
    scatter_kernel<<<NA / 256, 256>>>();

    gemm1_kernel<<<dim3(16, G1_NYP + G1_NYC, TE), 256, G1_SMEM>>>(
        0, 0, (const float4*)Wg, (const float4*)Wu, (const float4*)Wd);
    gemm1_kernel<<<dim3(16, G1_NYP + G1_NYC, TE), 256, G1_SMEM>>>(
        TF / 2, 1, (const float4*)Wg, (const float4*)Wu, (const float4*)Wd);

    gemm2_kernel<<<dim3(16, (TD / 128) * 2, TE), 256, G2_SMEM>>>();

    combine_kernel<<<(TT * TD / 2) / 256, 256>>>((float2*)out);
}